// round 1
// baseline (speedup 1.0000x reference)
#include <cuda_runtime.h>
#include <math.h>

// Problem constants (fixed shapes per metadata)
#define N_PTS   8192
#define M_GRID  32768
#define KNN     16
#define CIN     32
#define COUT    64
#define CPROV   96

// Scratch (static __device__ allocations are allowed)
__device__ float4 d_pts[N_PTS];                 // x,y,z,|r|^2
__device__ float  d_pf[N_PTS * COUT];           // features @ ew1[:32] + eb1
__device__ int    d_knn[M_GRID * KNN];
__device__ float  d_gmean[M_GRID * COUT];       // mean_k gelu(LN(...))
__device__ float  d_Wf[64 * 64];                // ew2 @ ow1[:64]
__device__ float  d_bf[64];                     // eb2 @ ow1[:64] + ob1

// ---------------------------------------------------------------- pack points
__global__ void k_pack(const float* __restrict__ verts) {
    int n = blockIdx.x * blockDim.x + threadIdx.x;
    if (n < N_PTS) {
        float x = verts[n * 3 + 0];
        float y = verts[n * 3 + 1];
        float z = verts[n * 3 + 2];
        d_pts[n] = make_float4(x, y, z, fmaf(x, x, fmaf(y, y, z * z)));
    }
}

// ------------------------------------------------- per-point feature precompute
__global__ void k_pf(const float* __restrict__ feat,
                     const float* __restrict__ ew1,
                     const float* __restrict__ eb1) {
    int id = blockIdx.x * blockDim.x + threadIdx.x;   // N_PTS*64 threads
    if (id >= N_PTS * COUT) return;
    int n = id >> 6, c = id & 63;
    float s = eb1[c];
    const float* f = feat + n * CIN;
#pragma unroll
    for (int j = 0; j < CIN; j++)
        s = fmaf(__ldg(&f[j]), __ldg(&ew1[j * 64 + c]), s);
    d_pf[id] = s;
}

// --------------------------------------------------- fused out-MLP weight/bias
__global__ void k_fuse(const float* __restrict__ ew2,
                       const float* __restrict__ eb2,
                       const float* __restrict__ ow1,
                       const float* __restrict__ ob1) {
    int id = blockIdx.x * blockDim.x + threadIdx.x;   // 4096 threads
    if (id >= 64 * 64) return;
    int j = id >> 6, c = id & 63;
    float s = 0.f;
#pragma unroll
    for (int r = 0; r < 64; r++)
        s = fmaf(__ldg(&ew2[j * 64 + r]), __ldg(&ow1[r * 64 + c]), s);
    d_Wf[id] = s;
    if (j == 0) {
        float b = ob1[c];
#pragma unroll
        for (int r = 0; r < 64; r++)
            b = fmaf(__ldg(&eb2[r]), __ldg(&ow1[r * 64 + c]), b);
        d_bf[c] = b;
    }
}

// ---------------------------------------------------------------------- KNN
// score = |r|^2 - 2 q.r  (monotone in distance; uniform SCALER preserved order)
__device__ __forceinline__ void ins16(float s, int idx, float bv[16], int bi[16]) {
#pragma unroll
    for (int j = 15; j >= 1; --j) {
        if (s < bv[j - 1])      { bv[j] = bv[j - 1]; bi[j] = bi[j - 1]; }
        else if (s < bv[j])     { bv[j] = s;         bi[j] = idx; }
    }
    if (s < bv[0]) { bv[0] = s; bi[0] = idx; }
}

#define KNN_TILE 2048
__global__ __launch_bounds__(256) void k_knn(const float* __restrict__ gv) {
    __shared__ float4 sp[KNN_TILE];
    int m = blockIdx.x * blockDim.x + threadIdx.x;    // 32768 threads total
    float qx = -2.f * gv[m * 3 + 0];
    float qy = -2.f * gv[m * 3 + 1];
    float qz = -2.f * gv[m * 3 + 2];

    float bv[16]; int bi[16];
#pragma unroll
    for (int j = 0; j < 16; j++) { bv[j] = 3.4e38f; bi[j] = 0; }

    for (int base = 0; base < N_PTS; base += KNN_TILE) {
        __syncthreads();
        for (int i = threadIdx.x; i < KNN_TILE; i += 256)
            sp[i] = d_pts[base + i];
        __syncthreads();

        for (int i = 0; i < KNN_TILE; i += 4) {
            float4 p0 = sp[i + 0], p1 = sp[i + 1], p2 = sp[i + 2], p3 = sp[i + 3];
            float s0 = fmaf(qx, p0.x, fmaf(qy, p0.y, fmaf(qz, p0.z, p0.w)));
            float s1 = fmaf(qx, p1.x, fmaf(qy, p1.y, fmaf(qz, p1.z, p1.w)));
            float s2 = fmaf(qx, p2.x, fmaf(qy, p2.y, fmaf(qz, p2.z, p2.w)));
            float s3 = fmaf(qx, p3.x, fmaf(qy, p3.y, fmaf(qz, p3.z, p3.w)));
            if (s0 < bv[15]) ins16(s0, base + i + 0, bv, bi);
            if (s1 < bv[15]) ins16(s1, base + i + 1, bv, bi);
            if (s2 < bv[15]) ins16(s2, base + i + 2, bv, bi);
            if (s3 < bv[15]) ins16(s3, base + i + 3, bv, bi);
        }
    }
    int4* o = reinterpret_cast<int4*>(d_knn + m * 16);
    o[0] = make_int4(bi[0],  bi[1],  bi[2],  bi[3]);
    o[1] = make_int4(bi[4],  bi[5],  bi[6],  bi[7]);
    o[2] = make_int4(bi[8],  bi[9],  bi[10], bi[11]);
    o[3] = make_int4(bi[12], bi[13], bi[14], bi[15]);
}

// -------------------------------------------------- edge MLP + mean over K
// thread = (m, k); 16 threads per m; block = 128 threads = 8 m
__device__ __forceinline__ float gelu_t(float x) {
    // tanh-approx gelu = x * sigmoid(2*sqrt(2/pi)*(x + 0.044715 x^3))
    float a = -1.5957691216057308f * x * fmaf(0.044715f, x * x, 1.f);
    float e = __expf(a);
    return __fdividef(x, 1.f + e);
}

__global__ __launch_bounds__(128) void k_edge(const float* __restrict__ verts,
                                              const float* __restrict__ gv,
                                              const float* __restrict__ ew1,
                                              const float* __restrict__ eg1,
                                              const float* __restrict__ ebt1) {
    __shared__ float sW[3 * 64];
    __shared__ float sg[64], sb[64];
    int t = threadIdx.x;
    for (int i = t; i < 192; i += 128) sW[i] = ew1[32 * 64 + i];
    if (t < 64) { sg[t] = eg1[t]; sb[t] = ebt1[t]; }
    __syncthreads();

    int gid = blockIdx.x * 128 + t;
    int m = gid >> 4;
    int idx = d_knn[gid];

    float gx = gv[m * 3 + 0], gy = gv[m * 3 + 1], gz = gv[m * 3 + 2];
    float rx = verts[idx * 3 + 0] - gx;
    float ry = verts[idx * 3 + 1] - gy;
    float rz = verts[idx * 3 + 2] - gz;

    float v[64];
    const float4* pfr = reinterpret_cast<const float4*>(d_pf + (size_t)idx * 64);
#pragma unroll
    for (int j = 0; j < 16; j++) {
        float4 p = pfr[j];
        int c = j * 4;
        v[c + 0] = fmaf(rx, sW[c + 0], fmaf(ry, sW[64 + c + 0], fmaf(rz, sW[128 + c + 0], p.x)));
        v[c + 1] = fmaf(rx, sW[c + 1], fmaf(ry, sW[64 + c + 1], fmaf(rz, sW[128 + c + 1], p.y)));
        v[c + 2] = fmaf(rx, sW[c + 2], fmaf(ry, sW[64 + c + 2], fmaf(rz, sW[128 + c + 2], p.z)));
        v[c + 3] = fmaf(rx, sW[c + 3], fmaf(ry, sW[64 + c + 3], fmaf(rz, sW[128 + c + 3], p.w)));
    }
    // LayerNorm over 64 channels (local)
    float s1 = 0.f;
#pragma unroll
    for (int j = 0; j < 64; j++) s1 += v[j];
    float mu = s1 * (1.f / 64.f);
    float s2 = 0.f;
#pragma unroll
    for (int j = 0; j < 64; j++) { float d = v[j] - mu; s2 = fmaf(d, d, s2); }
    float inv = rsqrtf(s2 * (1.f / 64.f) + 1e-5f);
#pragma unroll
    for (int j = 0; j < 64; j++) {
        float x = fmaf((v[j] - mu) * inv, sg[j], sb[j]);
        v[j] = gelu_t(x);
    }
    // mean over k=16 lanes (width-16 shuffle reduction)
#pragma unroll
    for (int off = 8; off > 0; off >>= 1) {
#pragma unroll
        for (int j = 0; j < 64; j++)
            v[j] += __shfl_down_sync(0xffffffffu, v[j], off, 16);
    }
    if ((t & 15) == 0) {
        float4* go = reinterpret_cast<float4*>(d_gmean + (size_t)m * 64);
#pragma unroll
        for (int j = 0; j < 16; j++)
            go[j] = make_float4(v[4 * j] * 0.0625f, v[4 * j + 1] * 0.0625f,
                                v[4 * j + 2] * 0.0625f, v[4 * j + 3] * 0.0625f);
    }
}

// ------------------------------------------------------------- out MLP
// warp handles 4 m; lane handles channels 2*lane, 2*lane+1
__global__ __launch_bounds__(256) void k_out(const float* __restrict__ gfeat,
                                             const float* __restrict__ ow1,
                                             const float* __restrict__ og1,
                                             const float* __restrict__ obt1,
                                             const float* __restrict__ ow2,
                                             const float* __restrict__ ob2,
                                             float* __restrict__ out) {
    extern __shared__ float smem[];
    float* sWf  = smem;               // 4096
    float* sW1b = sWf + 4096;         // 96*64 = 6144
    float* sW2  = sW1b + 6144;        // 4096
    float* sbf  = sW2 + 4096;         // 64
    float* sg1  = sbf + 64;
    float* sbt  = sg1 + 64;
    float* sb2  = sbt + 64;
    float* sbuf = sb2 + 64;           // 32 * 160

    int t = threadIdx.x;
    for (int i = t; i < 4096; i += 256) { sWf[i] = d_Wf[i]; sW2[i] = ow2[i]; }
    for (int i = t; i < 6144; i += 256) sW1b[i] = ow1[64 * 64 + i];
    if (t < 64) { sbf[t] = d_bf[t]; sg1[t] = og1[t]; sbt[t] = obt1[t]; sb2[t] = ob2[t]; }
    __syncthreads();

    int w = t >> 5, lane = t & 31;
    int mbase = blockIdx.x * 32 + w * 4;
    float* buf = sbuf + (w * 4) * 160;

#pragma unroll
    for (int q = 0; q < 4; q++) {
        int m = mbase + q;
        for (int i = lane; i < 64; i += 32) buf[q * 160 + i] = d_gmean[(size_t)m * 64 + i];
        for (int i = lane; i < 96; i += 32) buf[q * 160 + 64 + i] = gfeat[(size_t)m * 96 + i];
    }
    __syncwarp();

    int c0 = 2 * lane;
    float2 acc[4];
#pragma unroll
    for (int q = 0; q < 4; q++) acc[q] = make_float2(sbf[c0], sbf[c0 + 1]);

#pragma unroll 4
    for (int j = 0; j < 64; j++) {
        float2 wv = *reinterpret_cast<float2*>(&sWf[j * 64 + c0]);
#pragma unroll
        for (int q = 0; q < 4; q++) {
            float x = buf[q * 160 + j];
            acc[q].x = fmaf(x, wv.x, acc[q].x);
            acc[q].y = fmaf(x, wv.y, acc[q].y);
        }
    }
#pragma unroll 4
    for (int j = 0; j < 96; j++) {
        float2 wv = *reinterpret_cast<float2*>(&sW1b[j * 64 + c0]);
#pragma unroll
        for (int q = 0; q < 4; q++) {
            float x = buf[q * 160 + 64 + j];
            acc[q].x = fmaf(x, wv.x, acc[q].x);
            acc[q].y = fmaf(x, wv.y, acc[q].y);
        }
    }
    __syncwarp();   // all reads of buf done before reuse as activation storage

    float ga = sg1[c0], gb = sg1[c0 + 1], ba = sbt[c0], bb = sbt[c0 + 1];
#pragma unroll
    for (int q = 0; q < 4; q++) {
        float s1 = acc[q].x + acc[q].y;
        float s2 = fmaf(acc[q].x, acc[q].x, acc[q].y * acc[q].y);
#pragma unroll
        for (int off = 16; off > 0; off >>= 1) {
            s1 += __shfl_xor_sync(0xffffffffu, s1, off);
            s2 += __shfl_xor_sync(0xffffffffu, s2, off);
        }
        float mu  = s1 * (1.f / 64.f);
        float var = s2 * (1.f / 64.f) - mu * mu;
        float inv = rsqrtf(var + 1e-5f);
        float x0 = fmaf((acc[q].x - mu) * inv, ga, ba);
        float x1 = fmaf((acc[q].y - mu) * inv, gb, bb);
        buf[q * 160 + c0]     = gelu_t(x0);
        buf[q * 160 + c0 + 1] = gelu_t(x1);
    }
    __syncwarp();

    float2 o[4];
#pragma unroll
    for (int q = 0; q < 4; q++) o[q] = make_float2(sb2[c0], sb2[c0 + 1]);
#pragma unroll 4
    for (int j = 0; j < 64; j++) {
        float2 wv = *reinterpret_cast<float2*>(&sW2[j * 64 + c0]);
#pragma unroll
        for (int q = 0; q < 4; q++) {
            float x = buf[q * 160 + j];
            o[q].x = fmaf(x, wv.x, o[q].x);
            o[q].y = fmaf(x, wv.y, o[q].y);
        }
    }
#pragma unroll
    for (int q = 0; q < 4; q++) {
        int m = mbase + q;
        *reinterpret_cast<float2*>(&out[(size_t)m * 64 + c0]) = o[q];
    }
}

// ------------------------------------------------------------------ launch
extern "C" void kernel_launch(void* const* d_in, const int* in_sizes, int n_in,
                              void* d_out, int out_size) {
    const float* vertices = (const float*)d_in[0];
    const float* features = (const float*)d_in[1];
    const float* grid_v   = (const float*)d_in[2];
    const float* grid_f   = (const float*)d_in[3];
    const float* ew1  = (const float*)d_in[4];
    const float* eb1  = (const float*)d_in[5];
    const float* eg1  = (const float*)d_in[6];
    const float* ebt1 = (const float*)d_in[7];
    const float* ew2  = (const float*)d_in[8];
    const float* eb2  = (const float*)d_in[9];
    const float* ow1  = (const float*)d_in[10];
    const float* ob1  = (const float*)d_in[11];
    const float* og1  = (const float*)d_in[12];
    const float* obt1 = (const float*)d_in[13];
    const float* ow2  = (const float*)d_in[14];
    const float* ob2  = (const float*)d_in[15];
    float* out = (float*)d_out;

    const int OUT_SMEM = (4096 + 6144 + 4096 + 4 * 64 + 32 * 160) * (int)sizeof(float);
    cudaFuncSetAttribute(k_out, cudaFuncAttributeMaxDynamicSharedMemorySize, OUT_SMEM);

    k_pack<<<(N_PTS + 255) / 256, 256>>>(vertices);
    k_pf<<<(N_PTS * COUT + 255) / 256, 256>>>(features, ew1, eb1);
    k_fuse<<<16, 256>>>(ew2, eb2, ow1, ob1);
    k_knn<<<M_GRID / 256, 256>>>(grid_v);
    k_edge<<<(M_GRID * KNN) / 128, 128>>>(vertices, grid_v, ew1, eg1, ebt1);
    k_out<<<M_GRID / 32, 256, OUT_SMEM>>>(grid_f, ow1, og1, obt1, ow2, ob2, out);
}

// round 2
// speedup vs baseline: 1.5351x; 1.5351x over previous
#include <cuda_runtime.h>
#include <math.h>

// Problem constants (fixed shapes per metadata)
#define N_PTS   8192
#define M_GRID  32768
#define KNN     16
#define CIN     32
#define COUT    64
#define CPROV   96

#define NCELL_AX 8            // cells per axis
#define NCELLS   512
#define CS       4.0f         // scaled cell size (32 / 8)
#define CAP      1024         // smem candidate cap (avg ~430 for 27 cells)

// Scratch (static __device__ allocations are allowed)
__device__ int    d_cnt[NCELLS];
__device__ int    d_cellstart[NCELLS + 1];
__device__ int    d_cell[N_PTS];
__device__ float4 d_spts[N_PTS];               // scaled x,y,z,|r|^2 (cell-sorted)
__device__ int    d_sidx[N_PTS];               // original index (cell-sorted)
__device__ float  d_pf[N_PTS * COUT];          // features @ ew1[:32] + eb1
__device__ int    d_knn[M_GRID * KNN];
__device__ float  d_gmean[M_GRID * COUT];      // mean_k gelu(LN(...))
__device__ float  d_Wf[64 * 64];               // ew2 @ ow1[:64]
__device__ float  d_bf[64];                    // eb2 @ ow1[:64] + ob1

// ------------------------------------------------------------ binning kernels
__global__ void k_zero() {
    int t = threadIdx.x;
    if (t < NCELLS) d_cnt[t] = 0;
}

__global__ void k_prep(const float* __restrict__ verts) {
    int n = blockIdx.x * blockDim.x + threadIdx.x;
    if (n >= N_PTS) return;
    float x = verts[n * 3 + 0], y = verts[n * 3 + 1], z = verts[n * 3 + 2];
    int cx = min(max((int)(x * 8.0f), 0), 7);
    int cy = min(max((int)(y * 8.0f), 0), 7);
    int cz = min(max((int)(z * 8.0f), 0), 7);
    int c = (cx * 8 + cy) * 8 + cz;
    d_cell[n] = c;
    atomicAdd(&d_cnt[c], 1);
}

__global__ void k_scan() {
    __shared__ int sc[NCELLS];
    int t = threadIdx.x;
    sc[t] = d_cnt[t];
    __syncthreads();
    for (int off = 1; off < NCELLS; off <<= 1) {
        int v = 0;
        if (t >= off) v = sc[t - off];
        __syncthreads();
        sc[t] += v;
        __syncthreads();
    }
    d_cellstart[t + 1] = sc[t];
    if (t == 0) d_cellstart[0] = 0;
}

// Deterministic scatter: block b owns cell b; thread t owns contiguous points
// [t*64, t*64+64) so within-cell order == ascending original index.
__global__ __launch_bounds__(128) void k_scatter(const float* __restrict__ verts) {
    int b = blockIdx.x;
    int t = threadIdx.x;
    int lo = t * 64, hi = lo + 64;
    int cnt = 0;
    for (int i = lo; i < hi; i++) cnt += (d_cell[i] == b);

    // block exclusive scan of cnt
    int lane = t & 31, w = t >> 5;
    int inc = cnt;
    for (int off = 1; off < 32; off <<= 1) {
        int v = __shfl_up_sync(0xffffffffu, inc, off);
        if (lane >= off) inc += v;
    }
    __shared__ int wtot[4];
    if (lane == 31) wtot[w] = inc;
    __syncthreads();
    int wbase = 0;
    for (int i = 0; i < w; i++) wbase += wtot[i];
    int dst = d_cellstart[b] + wbase + inc - cnt;

    for (int i = lo; i < hi; i++) {
        if (d_cell[i] == b) {
            float x = verts[i * 3 + 0] * 32.f;
            float y = verts[i * 3 + 1] * 32.f;
            float z = verts[i * 3 + 2] * 32.f;
            d_spts[dst] = make_float4(x, y, z, fmaf(x, x, fmaf(y, y, z * z)));
            d_sidx[dst] = i;
            dst++;
        }
    }
}

// ------------------------------------------------- per-point feature precompute
__global__ void k_pf(const float* __restrict__ feat,
                     const float* __restrict__ ew1,
                     const float* __restrict__ eb1) {
    int id = blockIdx.x * blockDim.x + threadIdx.x;
    if (id >= N_PTS * COUT) return;
    int n = id >> 6, c = id & 63;
    float s = eb1[c];
    const float* f = feat + n * CIN;
#pragma unroll
    for (int j = 0; j < CIN; j++)
        s = fmaf(__ldg(&f[j]), __ldg(&ew1[j * 64 + c]), s);
    d_pf[id] = s;
}

// --------------------------------------------------- fused out-MLP weight/bias
__global__ void k_fuse(const float* __restrict__ ew2,
                       const float* __restrict__ eb2,
                       const float* __restrict__ ow1,
                       const float* __restrict__ ob1) {
    int id = blockIdx.x * blockDim.x + threadIdx.x;
    if (id >= 64 * 64) return;
    int j = id >> 6, c = id & 63;
    float s = 0.f;
#pragma unroll
    for (int r = 0; r < 64; r++)
        s = fmaf(__ldg(&ew2[j * 64 + r]), __ldg(&ow1[r * 64 + c]), s);
    d_Wf[id] = s;
    if (j == 0) {
        float b = ob1[c];
#pragma unroll
        for (int r = 0; r < 64; r++)
            b = fmaf(__ldg(&eb2[r]), __ldg(&ow1[r * 64 + c]), b);
        d_bf[c] = b;
    }
}

// ---------------------------------------------------------------------- KNN
__device__ __forceinline__ void ins16(float s, int idx, float bv[16], int bi[16]) {
#pragma unroll
    for (int j = 15; j >= 1; --j) {
        if (s < bv[j - 1])      { bv[j] = bv[j - 1]; bi[j] = bi[j - 1]; }
        else if (s < bv[j])     { bv[j] = s;         bi[j] = idx; }
    }
    if (s < bv[0]) { bv[0] = s; bi[0] = idx; }
}

__device__ __forceinline__ void scan_run(int s, int e,
                                         float qx, float qy, float qz, float Q,
                                         float bv[16], int bi[16]) {
    for (int i = s; i < e; i++) {
        float4 p = __ldg(&d_spts[i]);
        float dotv = fmaf(qx, p.x, fmaf(qy, p.y, qz * p.z));
        float sc = (Q + p.w) - 2.f * dotv;
        if (sc < bv[15]) ins16(sc, __ldg(&d_sidx[i]), bv, bi);
    }
}

// block = one query cell (4x4x4 = 64 grid vertices); 27-cell neighborhood
// staged in smem as 9 contiguous z-runs; exact ring expansion beyond.
__global__ __launch_bounds__(64) void k_knn(const float* __restrict__ gv) {
    __shared__ float4 spos[CAP];
    __shared__ int    sidx[CAP];

    int b = blockIdx.x;
    int cx = b >> 6, cy = (b >> 3) & 7, cz = b & 7;
    int t = threadIdx.x;
    int sx = t >> 4, sy = (t >> 2) & 3, sz = t & 3;
    int gx = cx * 4 + sx, gy = cy * 4 + sy, gz = cz * 4 + sz;
    int m = (gx * 32 + gy) * 32 + gz;

    float qx = gv[m * 3 + 0] * 32.f;
    float qy = gv[m * 3 + 1] * 32.f;
    float qz = gv[m * 3 + 2] * 32.f;
    float Q = fmaf(qx, qx, fmaf(qy, qy, qz * qz));

    // stage ring-1 neighborhood (9 contiguous z-runs)
    int nc = 0;
    int zlo = max(cz - 1, 0), zhi = min(cz + 1, 7);
    for (int dx = -1; dx <= 1; dx++) {
        int x = cx + dx;
        if ((unsigned)x > 7u) continue;
        for (int dy = -1; dy <= 1; dy++) {
            int y = cy + dy;
            if ((unsigned)y > 7u) continue;
            int base = (x * 8 + y) * 8;
            int s = __ldg(&d_cellstart[base + zlo]);
            int e = __ldg(&d_cellstart[base + zhi + 1]);
            int len = e - s;
            if (nc + len > CAP) len = CAP - nc;
            for (int i = t; i < len; i += 64) {
                spos[nc + i] = d_spts[s + i];
                sidx[nc + i] = d_sidx[s + i];
            }
            nc += len;
        }
    }
    __syncthreads();

    float bv[16]; int bi[16];
#pragma unroll
    for (int j = 0; j < 16; j++) { bv[j] = 3.4e38f; bi[j] = 0; }

    for (int i = 0; i < nc; i++) {
        float4 p = spos[i];
        float dotv = fmaf(qx, p.x, fmaf(qy, p.y, qz * p.z));
        float sc = (Q + p.w) - 2.f * dotv;
        if (sc < bv[15]) ins16(sc, sidx[i], bv, bi);
    }

    // exact ring expansion: covered box after ring rr = cells [c-rr, c+rr]
    for (int rr = 1; rr < 8; rr++) {
        float mlx = (cx - rr > 0) ? qx - (float)(cx - rr) * CS : 1e30f;
        float mhx = (cx + rr < 7) ? (float)(cx + rr + 1) * CS - qx : 1e30f;
        float mly = (cy - rr > 0) ? qy - (float)(cy - rr) * CS : 1e30f;
        float mhy = (cy + rr < 7) ? (float)(cy + rr + 1) * CS - qy : 1e30f;
        float mlz = (cz - rr > 0) ? qz - (float)(cz - rr) * CS : 1e30f;
        float mhz = (cz + rr < 7) ? (float)(cz + rr + 1) * CS - qz : 1e30f;
        float mg = fminf(fminf(fminf(mlx, mhx), fminf(mly, mhy)), fminf(mlz, mhz));
        if (mg > 1e29f) break;                         // whole domain covered
        if (bv[15] <= mg * mg * 0.9999f) break;        // exact (with fp slack)

        int r2 = rr + 1;                               // scan Chebyshev shell r2
        for (int dx = -r2; dx <= r2; dx++) {
            int x = cx + dx;
            if ((unsigned)x > 7u) continue;
            for (int dy = -r2; dy <= r2; dy++) {
                int y = cy + dy;
                if ((unsigned)y > 7u) continue;
                int base = (x * 8 + y) * 8;
                if (max(abs(dx), abs(dy)) == r2) {
                    int zl = max(cz - r2, 0), zh = min(cz + r2, 7);
                    scan_run(__ldg(&d_cellstart[base + zl]),
                             __ldg(&d_cellstart[base + zh + 1]),
                             qx, qy, qz, Q, bv, bi);
                } else {
                    int z = cz - r2;
                    if (z >= 0)
                        scan_run(__ldg(&d_cellstart[base + z]),
                                 __ldg(&d_cellstart[base + z + 1]),
                                 qx, qy, qz, Q, bv, bi);
                    z = cz + r2;
                    if (z <= 7)
                        scan_run(__ldg(&d_cellstart[base + z]),
                                 __ldg(&d_cellstart[base + z + 1]),
                                 qx, qy, qz, Q, bv, bi);
                }
            }
        }
    }

    int4* o = reinterpret_cast<int4*>(d_knn + m * 16);
    o[0] = make_int4(bi[0],  bi[1],  bi[2],  bi[3]);
    o[1] = make_int4(bi[4],  bi[5],  bi[6],  bi[7]);
    o[2] = make_int4(bi[8],  bi[9],  bi[10], bi[11]);
    o[3] = make_int4(bi[12], bi[13], bi[14], bi[15]);
}

// -------------------------------------------------- edge MLP + mean over K
__device__ __forceinline__ float gelu_t(float x) {
    float a = -1.5957691216057308f * x * fmaf(0.044715f, x * x, 1.f);
    float e = __expf(a);
    return __fdividef(x, 1.f + e);
}

__global__ __launch_bounds__(128) void k_edge(const float* __restrict__ verts,
                                              const float* __restrict__ gv,
                                              const float* __restrict__ ew1,
                                              const float* __restrict__ eg1,
                                              const float* __restrict__ ebt1) {
    __shared__ float sW[3 * 64];
    __shared__ float sg[64], sb[64];
    int t = threadIdx.x;
    for (int i = t; i < 192; i += 128) sW[i] = ew1[32 * 64 + i];
    if (t < 64) { sg[t] = eg1[t]; sb[t] = ebt1[t]; }
    __syncthreads();

    int gid = blockIdx.x * 128 + t;
    int m = gid >> 4;
    int idx = d_knn[gid];

    float gx = gv[m * 3 + 0], gy = gv[m * 3 + 1], gz = gv[m * 3 + 2];
    float rx = verts[idx * 3 + 0] - gx;
    float ry = verts[idx * 3 + 1] - gy;
    float rz = verts[idx * 3 + 2] - gz;

    float v[64];
    const float4* pfr = reinterpret_cast<const float4*>(d_pf + (size_t)idx * 64);
#pragma unroll
    for (int j = 0; j < 16; j++) {
        float4 p = pfr[j];
        int c = j * 4;
        v[c + 0] = fmaf(rx, sW[c + 0], fmaf(ry, sW[64 + c + 0], fmaf(rz, sW[128 + c + 0], p.x)));
        v[c + 1] = fmaf(rx, sW[c + 1], fmaf(ry, sW[64 + c + 1], fmaf(rz, sW[128 + c + 1], p.y)));
        v[c + 2] = fmaf(rx, sW[c + 2], fmaf(ry, sW[64 + c + 2], fmaf(rz, sW[128 + c + 2], p.z)));
        v[c + 3] = fmaf(rx, sW[c + 3], fmaf(ry, sW[64 + c + 3], fmaf(rz, sW[128 + c + 3], p.w)));
    }
    float s1 = 0.f;
#pragma unroll
    for (int j = 0; j < 64; j++) s1 += v[j];
    float mu = s1 * (1.f / 64.f);
    float s2 = 0.f;
#pragma unroll
    for (int j = 0; j < 64; j++) { float d = v[j] - mu; s2 = fmaf(d, d, s2); }
    float inv = rsqrtf(s2 * (1.f / 64.f) + 1e-5f);
#pragma unroll
    for (int j = 0; j < 64; j++) {
        float x = fmaf((v[j] - mu) * inv, sg[j], sb[j]);
        v[j] = gelu_t(x);
    }
#pragma unroll
    for (int off = 8; off > 0; off >>= 1) {
#pragma unroll
        for (int j = 0; j < 64; j++)
            v[j] += __shfl_down_sync(0xffffffffu, v[j], off, 16);
    }
    if ((t & 15) == 0) {
        float4* go = reinterpret_cast<float4*>(d_gmean + (size_t)m * 64);
#pragma unroll
        for (int j = 0; j < 16; j++)
            go[j] = make_float4(v[4 * j] * 0.0625f, v[4 * j + 1] * 0.0625f,
                                v[4 * j + 2] * 0.0625f, v[4 * j + 3] * 0.0625f);
    }
}

// ------------------------------------------------------------- out MLP
__global__ __launch_bounds__(256) void k_out(const float* __restrict__ gfeat,
                                             const float* __restrict__ ow1,
                                             const float* __restrict__ og1,
                                             const float* __restrict__ obt1,
                                             const float* __restrict__ ow2,
                                             const float* __restrict__ ob2,
                                             float* __restrict__ out) {
    extern __shared__ float smem[];
    float* sWf  = smem;
    float* sW1b = sWf + 4096;
    float* sW2  = sW1b + 6144;
    float* sbf  = sW2 + 4096;
    float* sg1  = sbf + 64;
    float* sbt  = sg1 + 64;
    float* sb2  = sbt + 64;
    float* sbuf = sb2 + 64;

    int t = threadIdx.x;
    for (int i = t; i < 4096; i += 256) { sWf[i] = d_Wf[i]; sW2[i] = ow2[i]; }
    for (int i = t; i < 6144; i += 256) sW1b[i] = ow1[64 * 64 + i];
    if (t < 64) { sbf[t] = d_bf[t]; sg1[t] = og1[t]; sbt[t] = obt1[t]; sb2[t] = ob2[t]; }
    __syncthreads();

    int w = t >> 5, lane = t & 31;
    int mbase = blockIdx.x * 32 + w * 4;
    float* buf = sbuf + (w * 4) * 160;

#pragma unroll
    for (int q = 0; q < 4; q++) {
        int m = mbase + q;
        for (int i = lane; i < 64; i += 32) buf[q * 160 + i] = d_gmean[(size_t)m * 64 + i];
        for (int i = lane; i < 96; i += 32) buf[q * 160 + 64 + i] = gfeat[(size_t)m * 96 + i];
    }
    __syncwarp();

    int c0 = 2 * lane;
    float2 acc[4];
#pragma unroll
    for (int q = 0; q < 4; q++) acc[q] = make_float2(sbf[c0], sbf[c0 + 1]);

#pragma unroll 4
    for (int j = 0; j < 64; j++) {
        float2 wv = *reinterpret_cast<float2*>(&sWf[j * 64 + c0]);
#pragma unroll
        for (int q = 0; q < 4; q++) {
            float x = buf[q * 160 + j];
            acc[q].x = fmaf(x, wv.x, acc[q].x);
            acc[q].y = fmaf(x, wv.y, acc[q].y);
        }
    }
#pragma unroll 4
    for (int j = 0; j < 96; j++) {
        float2 wv = *reinterpret_cast<float2*>(&sW1b[j * 64 + c0]);
#pragma unroll
        for (int q = 0; q < 4; q++) {
            float x = buf[q * 160 + 64 + j];
            acc[q].x = fmaf(x, wv.x, acc[q].x);
            acc[q].y = fmaf(x, wv.y, acc[q].y);
        }
    }
    __syncwarp();

    float ga = sg1[c0], gb = sg1[c0 + 1], ba = sbt[c0], bb = sbt[c0 + 1];
#pragma unroll
    for (int q = 0; q < 4; q++) {
        float s1 = acc[q].x + acc[q].y;
        float s2 = fmaf(acc[q].x, acc[q].x, acc[q].y * acc[q].y);
#pragma unroll
        for (int off = 16; off > 0; off >>= 1) {
            s1 += __shfl_xor_sync(0xffffffffu, s1, off);
            s2 += __shfl_xor_sync(0xffffffffu, s2, off);
        }
        float mu  = s1 * (1.f / 64.f);
        float var = s2 * (1.f / 64.f) - mu * mu;
        float inv = rsqrtf(var + 1e-5f);
        float x0 = fmaf((acc[q].x - mu) * inv, ga, ba);
        float x1 = fmaf((acc[q].y - mu) * inv, gb, bb);
        buf[q * 160 + c0]     = gelu_t(x0);
        buf[q * 160 + c0 + 1] = gelu_t(x1);
    }
    __syncwarp();

    float2 o[4];
#pragma unroll
    for (int q = 0; q < 4; q++) o[q] = make_float2(sb2[c0], sb2[c0 + 1]);
#pragma unroll 4
    for (int j = 0; j < 64; j++) {
        float2 wv = *reinterpret_cast<float2*>(&sW2[j * 64 + c0]);
#pragma unroll
        for (int q = 0; q < 4; q++) {
            float x = buf[q * 160 + j];
            o[q].x = fmaf(x, wv.x, o[q].x);
            o[q].y = fmaf(x, wv.y, o[q].y);
        }
    }
#pragma unroll
    for (int q = 0; q < 4; q++) {
        int m = mbase + q;
        *reinterpret_cast<float2*>(&out[(size_t)m * 64 + c0]) = o[q];
    }
}

// ------------------------------------------------------------------ launch
extern "C" void kernel_launch(void* const* d_in, const int* in_sizes, int n_in,
                              void* d_out, int out_size) {
    const float* vertices = (const float*)d_in[0];
    const float* features = (const float*)d_in[1];
    const float* grid_v   = (const float*)d_in[2];
    const float* grid_f   = (const float*)d_in[3];
    const float* ew1  = (const float*)d_in[4];
    const float* eb1  = (const float*)d_in[5];
    const float* eg1  = (const float*)d_in[6];
    const float* ebt1 = (const float*)d_in[7];
    const float* ew2  = (const float*)d_in[8];
    const float* eb2  = (const float*)d_in[9];
    const float* ow1  = (const float*)d_in[10];
    const float* ob1  = (const float*)d_in[11];
    const float* og1  = (const float*)d_in[12];
    const float* obt1 = (const float*)d_in[13];
    const float* ow2  = (const float*)d_in[14];
    const float* ob2  = (const float*)d_in[15];
    float* out = (float*)d_out;

    const int OUT_SMEM = (4096 + 6144 + 4096 + 4 * 64 + 32 * 160) * (int)sizeof(float);
    cudaFuncSetAttribute(k_out, cudaFuncAttributeMaxDynamicSharedMemorySize, OUT_SMEM);

    k_zero<<<1, 512>>>();
    k_prep<<<(N_PTS + 255) / 256, 256>>>(vertices);
    k_scan<<<1, 512>>>();
    k_scatter<<<NCELLS, 128>>>(vertices);
    k_pf<<<(N_PTS * COUT + 255) / 256, 256>>>(features, ew1, eb1);
    k_fuse<<<16, 256>>>(ew2, eb2, ow1, ob1);
    k_knn<<<NCELLS, 64>>>(grid_v);
    k_edge<<<(M_GRID * KNN) / 128, 128>>>(vertices, grid_v, ew1, eg1, ebt1);
    k_out<<<M_GRID / 32, 256, OUT_SMEM>>>(grid_f, ow1, og1, obt1, ow2, ob2, out);
}

// round 5
// speedup vs baseline: 1.5709x; 1.0233x over previous
#include <cuda_runtime.h>
#include <math.h>

// Problem constants (fixed shapes per metadata)
#define N_PTS   8192
#define M_GRID  32768
#define KNN     16
#define CIN     32
#define COUT    64
#define CPROV   96

#define NCELLS   512
#define CS       4.0f         // scaled cell size (32 / 8)
#define CAP      1024         // smem candidate cap (avg ~430 for 27 cells)

// Scratch (static __device__ allocations are allowed)
__device__ int    d_cnt[NCELLS];
__device__ int    d_cnt2[NCELLS];
__device__ int    d_cellstart[NCELLS + 1];
__device__ int    d_cell[N_PTS];
__device__ float4 d_spts[N_PTS];               // scaled x,y,z,|r|^2 (cell-grouped)
__device__ int    d_sidx[N_PTS];               // original index (cell-grouped)
__device__ float  d_pf[N_PTS * COUT];          // features @ ew1[:32] + eb1
__device__ int    d_knn[M_GRID * KNN];
__device__ float  d_gmean[M_GRID * COUT];      // mean_k gelu(LN(...))
__device__ float  d_Wf[64 * 64];               // ew2 @ ow1[:64]
__device__ float  d_bf[64];                    // eb2 @ ow1[:64] + ob1

// ------------------------------------------- fused weights + counter zeroing
__global__ void k_fuse(const float* __restrict__ ew2,
                       const float* __restrict__ eb2,
                       const float* __restrict__ ow1,
                       const float* __restrict__ ob1) {
    int id = blockIdx.x * blockDim.x + threadIdx.x;   // 4096 threads
    if (id < NCELLS) d_cnt[id] = 0;
    else if (id < 2 * NCELLS) d_cnt2[id - NCELLS] = 0;
    if (id >= 64 * 64) return;
    int j = id >> 6, c = id & 63;
    float s = 0.f;
#pragma unroll
    for (int r = 0; r < 64; r++)
        s = fmaf(__ldg(&ew2[j * 64 + r]), __ldg(&ow1[r * 64 + c]), s);
    d_Wf[id] = s;
    if (j == 0) {
        float b = ob1[c];
#pragma unroll
        for (int r = 0; r < 64; r++)
            b = fmaf(__ldg(&eb2[r]), __ldg(&ow1[r * 64 + c]), b);
        d_bf[c] = b;
    }
}

// ------------------------------------------------------------ binning kernels
__global__ void k_prep(const float* __restrict__ verts) {
    int n = blockIdx.x * blockDim.x + threadIdx.x;
    if (n >= N_PTS) return;
    float x = verts[n * 3 + 0], y = verts[n * 3 + 1], z = verts[n * 3 + 2];
    int cx = min(max((int)(x * 8.0f), 0), 7);
    int cy = min(max((int)(y * 8.0f), 0), 7);
    int cz = min(max((int)(z * 8.0f), 0), 7);
    int c = (cx * 8 + cy) * 8 + cz;
    d_cell[n] = c;
    atomicAdd(&d_cnt[c], 1);
}

__global__ void k_scan() {
    __shared__ int sc[NCELLS];
    int t = threadIdx.x;
    sc[t] = d_cnt[t];
    __syncthreads();
    for (int off = 1; off < NCELLS; off <<= 1) {
        int v = 0;
        if (t >= off) v = sc[t - off];
        __syncthreads();
        sc[t] += v;
        __syncthreads();
    }
    d_cellstart[t + 1] = sc[t];
    if (t == 0) d_cellstart[0] = 0;
}

// Atomic scatter: within-cell order is arbitrary, but the KNN top-16 SET is
// order-invariant (continuous data, no ties) and the edge mean kills order.
__global__ void k_scatter(const float* __restrict__ verts) {
    int n = blockIdx.x * blockDim.x + threadIdx.x;
    if (n >= N_PTS) return;
    int c = d_cell[n];
    int pos = d_cellstart[c] + atomicAdd(&d_cnt2[c], 1);
    float x = verts[n * 3 + 0] * 32.f;
    float y = verts[n * 3 + 1] * 32.f;
    float z = verts[n * 3 + 2] * 32.f;
    d_spts[pos] = make_float4(x, y, z, fmaf(x, x, fmaf(y, y, z * z)));
    d_sidx[pos] = n;
}

// ------------------------------------------------- per-point feature precompute
__global__ void k_pf(const float* __restrict__ feat,
                     const float* __restrict__ ew1,
                     const float* __restrict__ eb1) {
    int id = blockIdx.x * blockDim.x + threadIdx.x;
    if (id >= N_PTS * COUT) return;
    int n = id >> 6, c = id & 63;
    float s = eb1[c];
    const float* f = feat + n * CIN;
#pragma unroll
    for (int j = 0; j < CIN; j++)
        s = fmaf(__ldg(&f[j]), __ldg(&ew1[j * 64 + c]), s);
    d_pf[id] = s;
}

// ---------------------------------------------------------------------- KNN
__device__ __forceinline__ void ins16(float s, int idx, float bv[16], int bi[16]) {
#pragma unroll
    for (int j = 15; j >= 1; --j) {
        if (s < bv[j - 1])      { bv[j] = bv[j - 1]; bi[j] = bi[j - 1]; }
        else if (s < bv[j])     { bv[j] = s;         bi[j] = idx; }
    }
    if (s < bv[0]) { bv[0] = s; bi[0] = idx; }
}

// Race-free bitonic merge of the pair's two DISJOINT sorted lists.
// Snapshot partner's list reversed (shfl reads, writes go to separate buffer),
// elementwise min -> bitonic sequence holding the 16 smallest of the union,
// then 4-stage bitonic cleanup. Both threads end with the same merged list.
__device__ __forceinline__ void merge_final(float bv[16], int bi[16]) {
    float cv[16]; int ci[16];
#pragma unroll
    for (int j = 0; j < 16; j++) {
        float pv = __shfl_xor_sync(0xffffffffu, bv[15 - j], 1);
        int   pi = __shfl_xor_sync(0xffffffffu, bi[15 - j], 1);
        if (pv < bv[j]) { cv[j] = pv;    ci[j] = pi; }
        else            { cv[j] = bv[j]; ci[j] = bi[j]; }
    }
#pragma unroll
    for (int s = 8; s >= 1; s >>= 1) {
#pragma unroll
        for (int j = 0; j < 16; j++) {
            if ((j & s) == 0) {
                int k = j + s;
                if (cv[k] < cv[j]) {
                    float tv = cv[j]; cv[j] = cv[k]; cv[k] = tv;
                    int   ti = ci[j]; ci[j] = ci[k]; ci[k] = ti;
                }
            }
        }
    }
#pragma unroll
    for (int j = 0; j < 16; j++) { bv[j] = cv[j]; bi[j] = ci[j]; }
}

__device__ __forceinline__ void scan_run(int s, int e, int half,
                                         float qx, float qy, float qz, float Q,
                                         float bv[16], int bi[16]) {
    for (int i = s + half; i < e; i += 2) {
        float4 p = __ldg(&d_spts[i]);
        float dotv = fmaf(qx, p.x, fmaf(qy, p.y, qz * p.z));
        float sc = (Q + p.w) - 2.f * dotv;
        if (sc < bv[15]) ins16(sc, __ldg(&d_sidx[i]), bv, bi);
    }
}

// block = one query cell (64 grid vertices), 2 threads per query.
// Each thread of a pair scans its parity half of ALL candidates (ring-1 from
// smem, expansion shells from gmem) -> two disjoint partial lists, merged
// exactly once at the end. The expansion break test uses the thread's own
// partial kth (>= merged kth), so it is conservative, never wrong; if one
// thread breaks earlier, everything beyond its covered box is provably
// outside the merged top-16, so the partner's extra half-scans lose nothing.
__global__ __launch_bounds__(128) void k_knn(const float* __restrict__ gv) {
    __shared__ float4 spos[CAP];
    __shared__ int    sidx[CAP];

    int b = blockIdx.x;
    int cx = b >> 6, cy = (b >> 3) & 7, cz = b & 7;
    int t = threadIdx.x;
    int q = t >> 1, half = t & 1;
    int sx = q >> 4, sy = (q >> 2) & 3, sz = q & 3;
    int gx = cx * 4 + sx, gy = cy * 4 + sy, gz = cz * 4 + sz;
    int m = (gx * 32 + gy) * 32 + gz;

    float qx = gv[m * 3 + 0] * 32.f;
    float qy = gv[m * 3 + 1] * 32.f;
    float qz = gv[m * 3 + 2] * 32.f;
    float Q = fmaf(qx, qx, fmaf(qy, qy, qz * qz));

    // stage ring-1 neighborhood (9 contiguous z-runs)
    int nc = 0;
    int zlo = max(cz - 1, 0), zhi = min(cz + 1, 7);
    for (int dx = -1; dx <= 1; dx++) {
        int x = cx + dx;
        if ((unsigned)x > 7u) continue;
        for (int dy = -1; dy <= 1; dy++) {
            int y = cy + dy;
            if ((unsigned)y > 7u) continue;
            int base = (x * 8 + y) * 8;
            int s = __ldg(&d_cellstart[base + zlo]);
            int e = __ldg(&d_cellstart[base + zhi + 1]);
            int len = e - s;
            if (nc + len > CAP) len = CAP - nc;
            for (int i = t; i < len; i += 128) {
                spos[nc + i] = d_spts[s + i];
                sidx[nc + i] = d_sidx[s + i];
            }
            nc += len;
        }
    }
    __syncthreads();

    float bv[16]; int bi[16];
#pragma unroll
    for (int j = 0; j < 16; j++) { bv[j] = 3.4e38f; bi[j] = 0; }

    // split scan: this thread takes candidates half, half+2, ...
    for (int i = half; i < nc; i += 2) {
        float4 p = spos[i];
        float dotv = fmaf(qx, p.x, fmaf(qy, p.y, qz * p.z));
        float sc = (Q + p.w) - 2.f * dotv;
        if (sc < bv[15]) ins16(sc, sidx[i], bv, bi);
    }

    // exact ring expansion: covered box after ring rr = cells [c-rr, c+rr]
    for (int rr = 1; rr < 8; rr++) {
        float mlx = (cx - rr > 0) ? qx - (float)(cx - rr) * CS : 1e30f;
        float mhx = (cx + rr < 7) ? (float)(cx + rr + 1) * CS - qx : 1e30f;
        float mly = (cy - rr > 0) ? qy - (float)(cy - rr) * CS : 1e30f;
        float mhy = (cy + rr < 7) ? (float)(cy + rr + 1) * CS - qy : 1e30f;
        float mlz = (cz - rr > 0) ? qz - (float)(cz - rr) * CS : 1e30f;
        float mhz = (cz + rr < 7) ? (float)(cz + rr + 1) * CS - qz : 1e30f;
        float mg = fminf(fminf(fminf(mlx, mhx), fminf(mly, mhy)), fminf(mlz, mhz));
        if (mg > 1e29f) break;                         // whole domain covered
        if (bv[15] <= mg * mg * 0.9999f) break;        // conservative partial-kth test

        int r2 = rr + 1;                               // scan Chebyshev shell r2
        for (int dx = -r2; dx <= r2; dx++) {
            int x = cx + dx;
            if ((unsigned)x > 7u) continue;
            for (int dy = -r2; dy <= r2; dy++) {
                int y = cy + dy;
                if ((unsigned)y > 7u) continue;
                int base = (x * 8 + y) * 8;
                if (max(abs(dx), abs(dy)) == r2) {
                    int zl = max(cz - r2, 0), zh = min(cz + r2, 7);
                    scan_run(__ldg(&d_cellstart[base + zl]),
                             __ldg(&d_cellstart[base + zh + 1]), half,
                             qx, qy, qz, Q, bv, bi);
                } else {
                    int z = cz - r2;
                    if (z >= 0)
                        scan_run(__ldg(&d_cellstart[base + z]),
                                 __ldg(&d_cellstart[base + z + 1]), half,
                                 qx, qy, qz, Q, bv, bi);
                    z = cz + r2;
                    if (z <= 7)
                        scan_run(__ldg(&d_cellstart[base + z]),
                                 __ldg(&d_cellstart[base + z + 1]), half,
                                 qx, qy, qz, Q, bv, bi);
                }
            }
        }
    }

    merge_final(bv, bi);    // single race-free merge of the disjoint pair lists

    if (half == 0) {
        int4* o = reinterpret_cast<int4*>(d_knn + m * 16);
        o[0] = make_int4(bi[0],  bi[1],  bi[2],  bi[3]);
        o[1] = make_int4(bi[4],  bi[5],  bi[6],  bi[7]);
        o[2] = make_int4(bi[8],  bi[9],  bi[10], bi[11]);
        o[3] = make_int4(bi[12], bi[13], bi[14], bi[15]);
    }
}

// -------------------------------------------------- edge MLP + mean over K
__device__ __forceinline__ float gelu_t(float x) {
    float a = -1.5957691216057308f * x * fmaf(0.044715f, x * x, 1.f);
    float e = __expf(a);
    return __fdividef(x, 1.f + e);
}

__global__ __launch_bounds__(128) void k_edge(const float* __restrict__ verts,
                                              const float* __restrict__ gv,
                                              const float* __restrict__ ew1,
                                              const float* __restrict__ eg1,
                                              const float* __restrict__ ebt1) {
    __shared__ float sW[3 * 64];
    __shared__ float sg[64], sb[64];
    int t = threadIdx.x;
    for (int i = t; i < 192; i += 128) sW[i] = ew1[32 * 64 + i];
    if (t < 64) { sg[t] = eg1[t]; sb[t] = ebt1[t]; }
    __syncthreads();

    int gid = blockIdx.x * 128 + t;
    int m = gid >> 4;
    int idx = d_knn[gid];

    float gx = gv[m * 3 + 0], gy = gv[m * 3 + 1], gz = gv[m * 3 + 2];
    float rx = verts[idx * 3 + 0] - gx;
    float ry = verts[idx * 3 + 1] - gy;
    float rz = verts[idx * 3 + 2] - gz;

    float v[64];
    const float4* pfr = reinterpret_cast<const float4*>(d_pf + (size_t)idx * 64);
#pragma unroll
    for (int j = 0; j < 16; j++) {
        float4 p = pfr[j];
        int c = j * 4;
        v[c + 0] = fmaf(rx, sW[c + 0], fmaf(ry, sW[64 + c + 0], fmaf(rz, sW[128 + c + 0], p.x)));
        v[c + 1] = fmaf(rx, sW[c + 1], fmaf(ry, sW[64 + c + 1], fmaf(rz, sW[128 + c + 1], p.y)));
        v[c + 2] = fmaf(rx, sW[c + 2], fmaf(ry, sW[64 + c + 2], fmaf(rz, sW[128 + c + 2], p.z)));
        v[c + 3] = fmaf(rx, sW[c + 3], fmaf(ry, sW[64 + c + 3], fmaf(rz, sW[128 + c + 3], p.w)));
    }
    float s1 = 0.f;
#pragma unroll
    for (int j = 0; j < 64; j++) s1 += v[j];
    float mu = s1 * (1.f / 64.f);
    float s2 = 0.f;
#pragma unroll
    for (int j = 0; j < 64; j++) { float d = v[j] - mu; s2 = fmaf(d, d, s2); }
    float inv = rsqrtf(s2 * (1.f / 64.f) + 1e-5f);
#pragma unroll
    for (int j = 0; j < 64; j++) {
        float x = fmaf((v[j] - mu) * inv, sg[j], sb[j]);
        v[j] = gelu_t(x);
    }

    // mean over K: exchange-halves butterfly. After 4 steps, lane16 = t&15
    // holds channels [4*lane16, 4*lane16+4) summed over all 16 neighbors.
    int lane16 = t & 15;
#pragma unroll
    for (int halfc = 32; halfc >= 4; halfc >>= 1) {
        int bit = halfc >> 2;             // 8,4,2,1
        bool hi = (lane16 & bit) != 0;
#pragma unroll
        for (int j = 0; j < halfc; j++) {
            float send = hi ? v[j] : v[j + halfc];
            float r = __shfl_xor_sync(0xffffffffu, send, bit);
            v[j] = (hi ? v[j + halfc] : v[j]) + r;
        }
    }
    float4* go = reinterpret_cast<float4*>(d_gmean + (size_t)m * 64);
    go[lane16] = make_float4(v[0] * 0.0625f, v[1] * 0.0625f,
                             v[2] * 0.0625f, v[3] * 0.0625f);
}

// ------------------------------------------------------------- out MLP
__global__ __launch_bounds__(256) void k_out(const float* __restrict__ gfeat,
                                             const float* __restrict__ ow1,
                                             const float* __restrict__ og1,
                                             const float* __restrict__ obt1,
                                             const float* __restrict__ ow2,
                                             const float* __restrict__ ob2,
                                             float* __restrict__ out) {
    extern __shared__ float smem[];
    float* sWf  = smem;
    float* sW1b = sWf + 4096;
    float* sW2  = sW1b + 6144;
    float* sbf  = sW2 + 4096;
    float* sg1  = sbf + 64;
    float* sbt  = sg1 + 64;
    float* sb2  = sbt + 64;
    float* sbuf = sb2 + 64;

    int t = threadIdx.x;
    for (int i = t; i < 4096; i += 256) { sWf[i] = d_Wf[i]; sW2[i] = ow2[i]; }
    for (int i = t; i < 6144; i += 256) sW1b[i] = ow1[64 * 64 + i];
    if (t < 64) { sbf[t] = d_bf[t]; sg1[t] = og1[t]; sbt[t] = obt1[t]; sb2[t] = ob2[t]; }
    __syncthreads();

    int w = t >> 5, lane = t & 31;
    int mbase = blockIdx.x * 32 + w * 4;
    float* buf = sbuf + (w * 4) * 160;

#pragma unroll
    for (int q = 0; q < 4; q++) {
        int m = mbase + q;
        for (int i = lane; i < 64; i += 32) buf[q * 160 + i] = d_gmean[(size_t)m * 64 + i];
        for (int i = lane; i < 96; i += 32) buf[q * 160 + 64 + i] = gfeat[(size_t)m * 96 + i];
    }
    __syncwarp();

    int c0 = 2 * lane;
    float2 acc[4];
#pragma unroll
    for (int q = 0; q < 4; q++) acc[q] = make_float2(sbf[c0], sbf[c0 + 1]);

#pragma unroll 4
    for (int j = 0; j < 64; j++) {
        float2 wv = *reinterpret_cast<float2*>(&sWf[j * 64 + c0]);
#pragma unroll
        for (int q = 0; q < 4; q++) {
            float x = buf[q * 160 + j];
            acc[q].x = fmaf(x, wv.x, acc[q].x);
            acc[q].y = fmaf(x, wv.y, acc[q].y);
        }
    }
#pragma unroll 4
    for (int j = 0; j < 96; j++) {
        float2 wv = *reinterpret_cast<float2*>(&sW1b[j * 64 + c0]);
#pragma unroll
        for (int q = 0; q < 4; q++) {
            float x = buf[q * 160 + 64 + j];
            acc[q].x = fmaf(x, wv.x, acc[q].x);
            acc[q].y = fmaf(x, wv.y, acc[q].y);
        }
    }
    __syncwarp();

    float ga = sg1[c0], gb = sg1[c0 + 1], ba = sbt[c0], bb = sbt[c0 + 1];
#pragma unroll
    for (int q = 0; q < 4; q++) {
        float s1 = acc[q].x + acc[q].y;
        float s2 = fmaf(acc[q].x, acc[q].x, acc[q].y * acc[q].y);
#pragma unroll
        for (int off = 16; off > 0; off >>= 1) {
            s1 += __shfl_xor_sync(0xffffffffu, s1, off);
            s2 += __shfl_xor_sync(0xffffffffu, s2, off);
        }
        float mu  = s1 * (1.f / 64.f);
        float var = s2 * (1.f / 64.f) - mu * mu;
        float inv = rsqrtf(var + 1e-5f);
        float x0 = fmaf((acc[q].x - mu) * inv, ga, ba);
        float x1 = fmaf((acc[q].y - mu) * inv, gb, bb);
        buf[q * 160 + c0]     = gelu_t(x0);
        buf[q * 160 + c0 + 1] = gelu_t(x1);
    }
    __syncwarp();

    float2 o[4];
#pragma unroll
    for (int q = 0; q < 4; q++) o[q] = make_float2(sb2[c0], sb2[c0 + 1]);
#pragma unroll 4
    for (int j = 0; j < 64; j++) {
        float2 wv = *reinterpret_cast<float2*>(&sW2[j * 64 + c0]);
#pragma unroll
        for (int q = 0; q < 4; q++) {
            float x = buf[q * 160 + j];
            o[q].x = fmaf(x, wv.x, o[q].x);
            o[q].y = fmaf(x, wv.y, o[q].y);
        }
    }
#pragma unroll
    for (int q = 0; q < 4; q++) {
        int m = mbase + q;
        *reinterpret_cast<float2*>(&out[(size_t)m * 64 + c0]) = o[q];
    }
}

// ------------------------------------------------------------------ launch
extern "C" void kernel_launch(void* const* d_in, const int* in_sizes, int n_in,
                              void* d_out, int out_size) {
    const float* vertices = (const float*)d_in[0];
    const float* features = (const float*)d_in[1];
    const float* grid_v   = (const float*)d_in[2];
    const float* grid_f   = (const float*)d_in[3];
    const float* ew1  = (const float*)d_in[4];
    const float* eb1  = (const float*)d_in[5];
    const float* eg1  = (const float*)d_in[6];
    const float* ebt1 = (const float*)d_in[7];
    const float* ew2  = (const float*)d_in[8];
    const float* eb2  = (const float*)d_in[9];
    const float* ow1  = (const float*)d_in[10];
    const float* ob1  = (const float*)d_in[11];
    const float* og1  = (const float*)d_in[12];
    const float* obt1 = (const float*)d_in[13];
    const float* ow2  = (const float*)d_in[14];
    const float* ob2  = (const float*)d_in[15];
    float* out = (float*)d_out;

    const int OUT_SMEM = (4096 + 6144 + 4096 + 4 * 64 + 32 * 160) * (int)sizeof(float);
    cudaFuncSetAttribute(k_out, cudaFuncAttributeMaxDynamicSharedMemorySize, OUT_SMEM);

    k_fuse<<<16, 256>>>(ew2, eb2, ow1, ob1);               // also zeroes counters
    k_prep<<<(N_PTS + 255) / 256, 256>>>(vertices);
    k_scan<<<1, 512>>>();
    k_scatter<<<(N_PTS + 255) / 256, 256>>>(vertices);
    k_pf<<<(N_PTS * COUT + 255) / 256, 256>>>(features, ew1, eb1);
    k_knn<<<NCELLS, 128>>>(grid_v);
    k_edge<<<(M_GRID * KNN) / 128, 128>>>(vertices, grid_v, ew1, eg1, ebt1);
    k_out<<<M_GRID / 32, 256, OUT_SMEM>>>(grid_f, ow1, og1, obt1, ow2, ob2, out);
}

// round 6
// speedup vs baseline: 1.7969x; 1.1438x over previous
#include <cuda_runtime.h>
#include <math.h>

// Problem constants (fixed shapes per metadata)
#define N_PTS   8192
#define M_GRID  32768
#define KNN     16
#define CIN     32
#define COUT    64
#define CPROV   96

#define NCELLS   512
#define CS       4.0f         // scaled cell size (32 / 8)
#define CAP      1024         // smem candidate cap (avg ~430 for 27 cells)

// Scratch (static __device__ allocations are allowed)
__device__ int    d_cellstart[NCELLS + 1];
__device__ float4 d_spts[N_PTS];               // scaled x,y,z,|r|^2 (cell-grouped)
__device__ int    d_sidx[N_PTS];               // original index (cell-grouped)
__device__ float  d_pf[N_PTS * COUT];          // features @ ew1[:32] + eb1
__device__ int    d_knn[M_GRID * KNN];
__device__ float  d_gmean[M_GRID * COUT];      // mean_k gelu(LN(...))
__device__ float  d_Wf[64 * 64];               // ew2 @ ow1[:64]
__device__ float  d_bf[64];                    // eb2 @ ow1[:64] + ob1

// --------------------------------------------------- fused out-MLP weight/bias
__global__ void k_fuse(const float* __restrict__ ew2,
                       const float* __restrict__ eb2,
                       const float* __restrict__ ow1,
                       const float* __restrict__ ob1) {
    int id = blockIdx.x * blockDim.x + threadIdx.x;   // 4096 threads
    if (id >= 64 * 64) return;
    int j = id >> 6, c = id & 63;
    float s = 0.f;
#pragma unroll
    for (int r = 0; r < 64; r++)
        s = fmaf(__ldg(&ew2[j * 64 + r]), __ldg(&ow1[r * 64 + c]), s);
    d_Wf[id] = s;
    if (j == 0) {
        float b = ob1[c];
#pragma unroll
        for (int r = 0; r < 64; r++)
            b = fmaf(__ldg(&eb2[r]), __ldg(&ow1[r * 64 + c]), b);
        d_bf[c] = b;
    }
}

// ------------------------------------------- fused binning: hist+scan+scatter
// Single block, 1024 threads. Within-cell order is arbitrary (atomics), but
// the KNN top-16 SET is order-invariant and the edge mean kills order.
__global__ __launch_bounds__(1024) void k_bin(const float* __restrict__ verts) {
    __shared__ unsigned short scell[N_PTS];   // 16KB
    __shared__ int shist[NCELLS];
    __shared__ int sscan[NCELLS];
    __shared__ int soff[NCELLS];
    int t = threadIdx.x;
    if (t < NCELLS) shist[t] = 0;
    __syncthreads();

    for (int p = t; p < N_PTS; p += 1024) {
        float x = verts[3 * p + 0], y = verts[3 * p + 1], z = verts[3 * p + 2];
        int cx = min(max((int)(x * 8.0f), 0), 7);
        int cy = min(max((int)(y * 8.0f), 0), 7);
        int cz = min(max((int)(z * 8.0f), 0), 7);
        int c = (cx * 8 + cy) * 8 + cz;
        scell[p] = (unsigned short)c;
        atomicAdd(&shist[c], 1);
    }
    __syncthreads();

    if (t < NCELLS) sscan[t] = shist[t];
    __syncthreads();
    for (int off = 1; off < NCELLS; off <<= 1) {
        int v = 0;
        if (t < NCELLS && t >= off) v = sscan[t - off];
        __syncthreads();
        if (t < NCELLS) sscan[t] += v;
        __syncthreads();
    }
    if (t < NCELLS) {
        d_cellstart[t + 1] = sscan[t];
        soff[t] = sscan[t] - shist[t];   // exclusive start
    }
    if (t == 0) d_cellstart[0] = 0;
    __syncthreads();

    for (int p = t; p < N_PTS; p += 1024) {
        int c = scell[p];
        int pos = atomicAdd(&soff[c], 1);
        float x = verts[3 * p + 0] * 32.f;
        float y = verts[3 * p + 1] * 32.f;
        float z = verts[3 * p + 2] * 32.f;
        d_spts[pos] = make_float4(x, y, z, fmaf(x, x, fmaf(y, y, z * z)));
        d_sidx[pos] = p;
    }
}

// ------------------------------------------------- per-point feature precompute
__global__ void k_pf(const float* __restrict__ feat,
                     const float* __restrict__ ew1,
                     const float* __restrict__ eb1) {
    int id = blockIdx.x * blockDim.x + threadIdx.x;
    if (id >= N_PTS * COUT) return;
    int n = id >> 6, c = id & 63;
    float s = eb1[c];
    const float* f = feat + n * CIN;
#pragma unroll
    for (int j = 0; j < CIN; j++)
        s = fmaf(__ldg(&f[j]), __ldg(&ew1[j * 64 + c]), s);
    d_pf[id] = s;
}

// ---------------------------------------------------------------------- KNN
__device__ __forceinline__ void ins16(float s, int idx, float bv[16], int bi[16]) {
#pragma unroll
    for (int j = 15; j >= 1; --j) {
        if (s < bv[j - 1])      { bv[j] = bv[j - 1]; bi[j] = bi[j - 1]; }
        else if (s < bv[j])     { bv[j] = s;         bi[j] = idx; }
    }
    if (s < bv[0]) { bv[0] = s; bi[0] = idx; }
}

__device__ __forceinline__ void scan_run(int s, int e,
                                         float qx, float qy, float qz, float Q,
                                         float bv[16], int bi[16]) {
    for (int i = s; i < e; i++) {
        float4 p = __ldg(&d_spts[i]);
        float dotv = fmaf(qx, p.x, fmaf(qy, p.y, qz * p.z));
        float sc = (Q + p.w) - 2.f * dotv;
        if (sc < bv[15]) ins16(sc, __ldg(&d_sidx[i]), bv, bi);
    }
}

// block = one query cell (64 grid vertices), 1 thread per query.
// 27-cell neighborhood staged in smem as 9 (x,y)-column runs, scanned in
// nearest-first order with per-run column lower bounds and per-candidate
// z-lower-bound pruning (both exact: skipped => dist >= current bv[15] >=
// final kth). Ring expansion beyond is exact, rare.
__global__ __launch_bounds__(64) void k_knn(const float* __restrict__ gv) {
    __shared__ float4 spos[CAP];
    __shared__ int    sidx[CAP];

    int b = blockIdx.x;
    int cx = b >> 6, cy = (b >> 3) & 7, cz = b & 7;
    int t = threadIdx.x;
    // warp shares a z-slab: lanes vary fastest in x,y
    int sx = t & 3, sy = (t >> 2) & 3, sz = t >> 4;
    int gx = cx * 4 + sx, gy = cy * 4 + sy, gz = cz * 4 + sz;
    int m = (gx * 32 + gy) * 32 + gz;

    float qx = gv[m * 3 + 0] * 32.f;
    float qy = gv[m * 3 + 1] * 32.f;
    float qz = gv[m * 3 + 2] * 32.f;
    float Q = fmaf(qx, qx, fmaf(qy, qy, qz * qz));

    // stage ring-1 neighborhood, nearest columns first
    const int odx[9] = {0,  1, -1,  0,  0,  1,  1, -1, -1};
    const int ody[9] = {0,  0,  0,  1, -1,  1, -1,  1, -1};
    int rO[9], rL[9], rdx[9], rdy[9];
    int nrun = 0, nc = 0;
    int zlo = max(cz - 1, 0), zhi = min(cz + 1, 7);
    for (int k = 0; k < 9; k++) {
        int x = cx + odx[k], y = cy + ody[k];
        if ((unsigned)x > 7u || (unsigned)y > 7u) continue;
        int base = (x * 8 + y) * 8;
        int s = __ldg(&d_cellstart[base + zlo]);
        int e = __ldg(&d_cellstart[base + zhi + 1]);
        int len = e - s;
        if (nc + len > CAP) len = CAP - nc;
        for (int i = t; i < len; i += 64) {
            spos[nc + i] = d_spts[s + i];
            sidx[nc + i] = d_sidx[s + i];
        }
        rO[nrun] = nc; rL[nrun] = len; rdx[nrun] = odx[k]; rdy[nrun] = ody[k];
        nc += len; nrun++;
    }
    __syncthreads();

    float bv[16]; int bi[16];
#pragma unroll
    for (int j = 0; j < 16; j++) { bv[j] = 3.4e38f; bi[j] = 0; }

    for (int r = 0; r < nrun; r++) {
        int dx = rdx[r], dy = rdy[r];
        float lbx = (dx > 0) ? ((float)(cx + 1) * CS - qx)
                  : (dx < 0 ? (qx - (float)cx * CS) : 0.f);
        float lby = (dy > 0) ? ((float)(cy + 1) * CS - qy)
                  : (dy < 0 ? (qy - (float)cy * CS) : 0.f);
        float colmin2 = fmaf(lbx, lbx, lby * lby);
        if (colmin2 >= bv[15]) continue;          // whole column can't qualify

        int s = rO[r], e = rO[r] + rL[r];
        for (int i = s; i < e; i++) {
            float4 p = spos[i];
            float dz = p.z - qz;
            float lb = fmaf(dz, dz, colmin2);     // lower bound on true d^2
            if (lb < bv[15]) {
                float dotv = fmaf(qx, p.x, fmaf(qy, p.y, qz * p.z));
                float sc = (Q + p.w) - 2.f * dotv;
                if (sc < bv[15]) ins16(sc, sidx[i], bv, bi);
            }
        }
    }

    // exact ring expansion: covered box after ring rr = cells [c-rr, c+rr]
    for (int rr = 1; rr < 8; rr++) {
        float mlx = (cx - rr > 0) ? qx - (float)(cx - rr) * CS : 1e30f;
        float mhx = (cx + rr < 7) ? (float)(cx + rr + 1) * CS - qx : 1e30f;
        float mly = (cy - rr > 0) ? qy - (float)(cy - rr) * CS : 1e30f;
        float mhy = (cy + rr < 7) ? (float)(cy + rr + 1) * CS - qy : 1e30f;
        float mlz = (cz - rr > 0) ? qz - (float)(cz - rr) * CS : 1e30f;
        float mhz = (cz + rr < 7) ? (float)(cz + rr + 1) * CS - qz : 1e30f;
        float mg = fminf(fminf(fminf(mlx, mhx), fminf(mly, mhy)), fminf(mlz, mhz));
        if (mg > 1e29f) break;                         // whole domain covered
        if (bv[15] <= mg * mg * 0.9999f) break;        // exact (with fp slack)

        int r2 = rr + 1;                               // scan Chebyshev shell r2
        for (int dx = -r2; dx <= r2; dx++) {
            int x = cx + dx;
            if ((unsigned)x > 7u) continue;
            for (int dy = -r2; dy <= r2; dy++) {
                int y = cy + dy;
                if ((unsigned)y > 7u) continue;
                int base = (x * 8 + y) * 8;
                if (max(abs(dx), abs(dy)) == r2) {
                    int zl = max(cz - r2, 0), zh = min(cz + r2, 7);
                    scan_run(__ldg(&d_cellstart[base + zl]),
                             __ldg(&d_cellstart[base + zh + 1]),
                             qx, qy, qz, Q, bv, bi);
                } else {
                    int z = cz - r2;
                    if (z >= 0)
                        scan_run(__ldg(&d_cellstart[base + z]),
                                 __ldg(&d_cellstart[base + z + 1]),
                                 qx, qy, qz, Q, bv, bi);
                    z = cz + r2;
                    if (z <= 7)
                        scan_run(__ldg(&d_cellstart[base + z]),
                                 __ldg(&d_cellstart[base + z + 1]),
                                 qx, qy, qz, Q, bv, bi);
                }
            }
        }
    }

    int4* o = reinterpret_cast<int4*>(d_knn + m * 16);
    o[0] = make_int4(bi[0],  bi[1],  bi[2],  bi[3]);
    o[1] = make_int4(bi[4],  bi[5],  bi[6],  bi[7]);
    o[2] = make_int4(bi[8],  bi[9],  bi[10], bi[11]);
    o[3] = make_int4(bi[12], bi[13], bi[14], bi[15]);
}

// -------------------------------------------------- edge MLP + mean over K
__device__ __forceinline__ float gelu_t(float x) {
    float a = -1.5957691216057308f * x * fmaf(0.044715f, x * x, 1.f);
    float e = __expf(a);
    return __fdividef(x, 1.f + e);
}

__global__ __launch_bounds__(128) void k_edge(const float* __restrict__ verts,
                                              const float* __restrict__ gv,
                                              const float* __restrict__ ew1,
                                              const float* __restrict__ eg1,
                                              const float* __restrict__ ebt1) {
    __shared__ float sW[3 * 64];
    __shared__ float sg[64], sb[64];
    int t = threadIdx.x;
    for (int i = t; i < 192; i += 128) sW[i] = ew1[32 * 64 + i];
    if (t < 64) { sg[t] = eg1[t]; sb[t] = ebt1[t]; }
    __syncthreads();

    int gid = blockIdx.x * 128 + t;
    int m = gid >> 4;
    int idx = d_knn[gid];

    float gx = gv[m * 3 + 0], gy = gv[m * 3 + 1], gz = gv[m * 3 + 2];
    float rx = verts[idx * 3 + 0] - gx;
    float ry = verts[idx * 3 + 1] - gy;
    float rz = verts[idx * 3 + 2] - gz;

    float v[64];
    const float4* pfr = reinterpret_cast<const float4*>(d_pf + (size_t)idx * 64);
#pragma unroll
    for (int j = 0; j < 16; j++) {
        float4 p = pfr[j];
        int c = j * 4;
        v[c + 0] = fmaf(rx, sW[c + 0], fmaf(ry, sW[64 + c + 0], fmaf(rz, sW[128 + c + 0], p.x)));
        v[c + 1] = fmaf(rx, sW[c + 1], fmaf(ry, sW[64 + c + 1], fmaf(rz, sW[128 + c + 1], p.y)));
        v[c + 2] = fmaf(rx, sW[c + 2], fmaf(ry, sW[64 + c + 2], fmaf(rz, sW[128 + c + 2], p.z)));
        v[c + 3] = fmaf(rx, sW[c + 3], fmaf(ry, sW[64 + c + 3], fmaf(rz, sW[128 + c + 3], p.w)));
    }
    float s1 = 0.f;
#pragma unroll
    for (int j = 0; j < 64; j++) s1 += v[j];
    float mu = s1 * (1.f / 64.f);
    float s2 = 0.f;
#pragma unroll
    for (int j = 0; j < 64; j++) { float d = v[j] - mu; s2 = fmaf(d, d, s2); }
    float inv = rsqrtf(s2 * (1.f / 64.f) + 1e-5f);
#pragma unroll
    for (int j = 0; j < 64; j++) {
        float x = fmaf((v[j] - mu) * inv, sg[j], sb[j]);
        v[j] = gelu_t(x);
    }

    // mean over K: exchange-halves butterfly. After 4 steps, lane16 = t&15
    // holds channels [4*lane16, 4*lane16+4) summed over all 16 neighbors.
    int lane16 = t & 15;
#pragma unroll
    for (int halfc = 32; halfc >= 4; halfc >>= 1) {
        int bit = halfc >> 2;             // 8,4,2,1
        bool hi = (lane16 & bit) != 0;
#pragma unroll
        for (int j = 0; j < halfc; j++) {
            float send = hi ? v[j] : v[j + halfc];
            float r = __shfl_xor_sync(0xffffffffu, send, bit);
            v[j] = (hi ? v[j + halfc] : v[j]) + r;
        }
    }
    float4* go = reinterpret_cast<float4*>(d_gmean + (size_t)m * 64);
    go[lane16] = make_float4(v[0] * 0.0625f, v[1] * 0.0625f,
                             v[2] * 0.0625f, v[3] * 0.0625f);
}

// ------------------------------------------------------------- out MLP
__global__ __launch_bounds__(256) void k_out(const float* __restrict__ gfeat,
                                             const float* __restrict__ ow1,
                                             const float* __restrict__ og1,
                                             const float* __restrict__ obt1,
                                             const float* __restrict__ ow2,
                                             const float* __restrict__ ob2,
                                             float* __restrict__ out) {
    extern __shared__ float smem[];
    float* sWf  = smem;
    float* sW1b = sWf + 4096;
    float* sW2  = sW1b + 6144;
    float* sbf  = sW2 + 4096;
    float* sg1  = sbf + 64;
    float* sbt  = sg1 + 64;
    float* sb2  = sbt + 64;
    float* sbuf = sb2 + 64;

    int t = threadIdx.x;
    for (int i = t; i < 4096; i += 256) { sWf[i] = d_Wf[i]; sW2[i] = ow2[i]; }
    for (int i = t; i < 6144; i += 256) sW1b[i] = ow1[64 * 64 + i];
    if (t < 64) { sbf[t] = d_bf[t]; sg1[t] = og1[t]; sbt[t] = obt1[t]; sb2[t] = ob2[t]; }
    __syncthreads();

    int w = t >> 5, lane = t & 31;
    int mbase = blockIdx.x * 32 + w * 4;
    float* buf = sbuf + (w * 4) * 160;

#pragma unroll
    for (int q = 0; q < 4; q++) {
        int m = mbase + q;
        for (int i = lane; i < 64; i += 32) buf[q * 160 + i] = d_gmean[(size_t)m * 64 + i];
        for (int i = lane; i < 96; i += 32) buf[q * 160 + 64 + i] = gfeat[(size_t)m * 96 + i];
    }
    __syncwarp();

    int c0 = 2 * lane;
    float2 acc[4];
#pragma unroll
    for (int q = 0; q < 4; q++) acc[q] = make_float2(sbf[c0], sbf[c0 + 1]);

#pragma unroll 4
    for (int j = 0; j < 64; j++) {
        float2 wv = *reinterpret_cast<float2*>(&sWf[j * 64 + c0]);
#pragma unroll
        for (int q = 0; q < 4; q++) {
            float x = buf[q * 160 + j];
            acc[q].x = fmaf(x, wv.x, acc[q].x);
            acc[q].y = fmaf(x, wv.y, acc[q].y);
        }
    }
#pragma unroll 4
    for (int j = 0; j < 96; j++) {
        float2 wv = *reinterpret_cast<float2*>(&sW1b[j * 64 + c0]);
#pragma unroll
        for (int q = 0; q < 4; q++) {
            float x = buf[q * 160 + 64 + j];
            acc[q].x = fmaf(x, wv.x, acc[q].x);
            acc[q].y = fmaf(x, wv.y, acc[q].y);
        }
    }
    __syncwarp();

    float ga = sg1[c0], gb = sg1[c0 + 1], ba = sbt[c0], bb = sbt[c0 + 1];
#pragma unroll
    for (int q = 0; q < 4; q++) {
        float s1 = acc[q].x + acc[q].y;
        float s2 = fmaf(acc[q].x, acc[q].x, acc[q].y * acc[q].y);
#pragma unroll
        for (int off = 16; off > 0; off >>= 1) {
            s1 += __shfl_xor_sync(0xffffffffu, s1, off);
            s2 += __shfl_xor_sync(0xffffffffu, s2, off);
        }
        float mu  = s1 * (1.f / 64.f);
        float var = s2 * (1.f / 64.f) - mu * mu;
        float inv = rsqrtf(var + 1e-5f);
        float x0 = fmaf((acc[q].x - mu) * inv, ga, ba);
        float x1 = fmaf((acc[q].y - mu) * inv, gb, bb);
        buf[q * 160 + c0]     = gelu_t(x0);
        buf[q * 160 + c0 + 1] = gelu_t(x1);
    }
    __syncwarp();

    float2 o[4];
#pragma unroll
    for (int q = 0; q < 4; q++) o[q] = make_float2(sb2[c0], sb2[c0 + 1]);
#pragma unroll 4
    for (int j = 0; j < 64; j++) {
        float2 wv = *reinterpret_cast<float2*>(&sW2[j * 64 + c0]);
#pragma unroll
        for (int q = 0; q < 4; q++) {
            float x = buf[q * 160 + j];
            o[q].x = fmaf(x, wv.x, o[q].x);
            o[q].y = fmaf(x, wv.y, o[q].y);
        }
    }
#pragma unroll
    for (int q = 0; q < 4; q++) {
        int m = mbase + q;
        *reinterpret_cast<float2*>(&out[(size_t)m * 64 + c0]) = o[q];
    }
}

// ------------------------------------------------------------------ launch
extern "C" void kernel_launch(void* const* d_in, const int* in_sizes, int n_in,
                              void* d_out, int out_size) {
    const float* vertices = (const float*)d_in[0];
    const float* features = (const float*)d_in[1];
    const float* grid_v   = (const float*)d_in[2];
    const float* grid_f   = (const float*)d_in[3];
    const float* ew1  = (const float*)d_in[4];
    const float* eb1  = (const float*)d_in[5];
    const float* eg1  = (const float*)d_in[6];
    const float* ebt1 = (const float*)d_in[7];
    const float* ew2  = (const float*)d_in[8];
    const float* eb2  = (const float*)d_in[9];
    const float* ow1  = (const float*)d_in[10];
    const float* ob1  = (const float*)d_in[11];
    const float* og1  = (const float*)d_in[12];
    const float* obt1 = (const float*)d_in[13];
    const float* ow2  = (const float*)d_in[14];
    const float* ob2  = (const float*)d_in[15];
    float* out = (float*)d_out;

    const int OUT_SMEM = (4096 + 6144 + 4096 + 4 * 64 + 32 * 160) * (int)sizeof(float);
    cudaFuncSetAttribute(k_out, cudaFuncAttributeMaxDynamicSharedMemorySize, OUT_SMEM);

    k_fuse<<<16, 256>>>(ew2, eb2, ow1, ob1);                 // launch 1
    k_bin<<<1, 1024>>>(vertices);                            // launch 2
    k_pf<<<(N_PTS * COUT + 255) / 256, 256>>>(features, ew1, eb1);  // launch 3
    k_knn<<<NCELLS, 64>>>(grid_v);                           // launch 4 (profiled)
    k_edge<<<(M_GRID * KNN) / 128, 128>>>(vertices, grid_v, ew1, eg1, ebt1);
    k_out<<<M_GRID / 32, 256, OUT_SMEM>>>(grid_f, ow1, og1, obt1, ow2, ob2, out);
}

// round 7
// speedup vs baseline: 1.8278x; 1.0172x over previous
#include <cuda_runtime.h>
#include <math.h>

// Problem constants (fixed shapes per metadata)
#define N_PTS   8192
#define M_GRID  32768
#define KNN     16
#define CIN     32
#define COUT    64
#define CPROV   96

#define NCELLS   512
#define CS       4.0f         // scaled cell size (32 / 8)
#define CAP      1024         // smem candidate cap (avg ~430 for 27 cells)

// Scratch (static __device__ allocations are allowed)
__device__ int    d_cellstart[NCELLS + 1];
__device__ float4 d_spts[N_PTS];               // scaled x,y,z,|r|^2 (cell-grouped)
__device__ int    d_sidx[N_PTS];               // original index (cell-grouped)
__device__ float  d_pf[N_PTS * COUT];          // features @ ew1[:32] + eb1
__device__ int    d_knn[M_GRID * KNN];
__device__ float  d_gmean[M_GRID * COUT];      // mean_k gelu(LN(...))
__device__ float  d_Wf[64 * 64];               // ew2 @ ow1[:64]
__device__ float  d_bf[64];                    // eb2 @ ow1[:64] + ob1

// --------------------------------------------------- fused out-MLP weight/bias
__global__ void k_fuse(const float* __restrict__ ew2,
                       const float* __restrict__ eb2,
                       const float* __restrict__ ow1,
                       const float* __restrict__ ob1) {
    int id = blockIdx.x * blockDim.x + threadIdx.x;   // 4096 threads
    if (id >= 64 * 64) return;
    int j = id >> 6, c = id & 63;
    float s = 0.f;
#pragma unroll
    for (int r = 0; r < 64; r++)
        s = fmaf(__ldg(&ew2[j * 64 + r]), __ldg(&ow1[r * 64 + c]), s);
    d_Wf[id] = s;
    if (j == 0) {
        float b = ob1[c];
#pragma unroll
        for (int r = 0; r < 64; r++)
            b = fmaf(__ldg(&eb2[r]), __ldg(&ow1[r * 64 + c]), b);
        d_bf[c] = b;
    }
}

// ------------------------------------------- fused binning: hist+scan+scatter
__global__ __launch_bounds__(1024) void k_bin(const float* __restrict__ verts) {
    __shared__ unsigned short scell[N_PTS];   // 16KB
    __shared__ int shist[NCELLS];
    __shared__ int sscan[NCELLS];
    __shared__ int soff[NCELLS];
    int t = threadIdx.x;
    if (t < NCELLS) shist[t] = 0;
    __syncthreads();

    for (int p = t; p < N_PTS; p += 1024) {
        float x = verts[3 * p + 0], y = verts[3 * p + 1], z = verts[3 * p + 2];
        int cx = min(max((int)(x * 8.0f), 0), 7);
        int cy = min(max((int)(y * 8.0f), 0), 7);
        int cz = min(max((int)(z * 8.0f), 0), 7);
        int c = (cx * 8 + cy) * 8 + cz;
        scell[p] = (unsigned short)c;
        atomicAdd(&shist[c], 1);
    }
    __syncthreads();

    if (t < NCELLS) sscan[t] = shist[t];
    __syncthreads();
    for (int off = 1; off < NCELLS; off <<= 1) {
        int v = 0;
        if (t < NCELLS && t >= off) v = sscan[t - off];
        __syncthreads();
        if (t < NCELLS) sscan[t] += v;
        __syncthreads();
    }
    if (t < NCELLS) {
        d_cellstart[t + 1] = sscan[t];
        soff[t] = sscan[t] - shist[t];   // exclusive start
    }
    if (t == 0) d_cellstart[0] = 0;
    __syncthreads();

    for (int p = t; p < N_PTS; p += 1024) {
        int c = scell[p];
        int pos = atomicAdd(&soff[c], 1);
        float x = verts[3 * p + 0] * 32.f;
        float y = verts[3 * p + 1] * 32.f;
        float z = verts[3 * p + 2] * 32.f;
        d_spts[pos] = make_float4(x, y, z, fmaf(x, x, fmaf(y, y, z * z)));
        d_sidx[pos] = p;
    }
}

// ------------------------------------------------- per-point feature precompute
__global__ void k_pf(const float* __restrict__ feat,
                     const float* __restrict__ ew1,
                     const float* __restrict__ eb1) {
    int id = blockIdx.x * blockDim.x + threadIdx.x;
    if (id >= N_PTS * COUT) return;
    int n = id >> 6, c = id & 63;
    float s = eb1[c];
    const float* f = feat + n * CIN;
#pragma unroll
    for (int j = 0; j < CIN; j++)
        s = fmaf(__ldg(&f[j]), __ldg(&ew1[j * 64 + c]), s);
    d_pf[id] = s;
}

// ---------------------------------------------------------------------- KNN
__device__ __forceinline__ void ins16(float s, int idx, float bv[16], int bi[16]) {
#pragma unroll
    for (int j = 15; j >= 1; --j) {
        if (s < bv[j - 1])      { bv[j] = bv[j - 1]; bi[j] = bi[j - 1]; }
        else if (s < bv[j])     { bv[j] = s;         bi[j] = idx; }
    }
    if (s < bv[0]) { bv[0] = s; bi[0] = idx; }
}

__device__ __forceinline__ void scan_run(int s, int e,
                                         float qx, float qy, float qz, float Q,
                                         float bv[16], int bi[16]) {
    for (int i = s; i < e; i++) {
        float4 p = __ldg(&d_spts[i]);
        float dotv = fmaf(qx, p.x, fmaf(qy, p.y, qz * p.z));
        float sc = (Q + p.w) - 2.f * dotv;
        if (sc < bv[15]) ins16(sc, __ldg(&d_sidx[i]), bv, bi);
    }
}

// block = one query cell (64 grid vertices), 1 thread per query.
// 27-cell neighborhood staged in smem as 9 (x,y)-column runs; a 27-entry
// sub-run table (one per z-cell chunk, ~16 pts) carries exact lower bounds
// so whole chunks are skipped when they can't beat the current 16th distance.
// Skips are exact: lb2 >= bv[15] => every point in chunk has d^2 >= 16 seen
// values. Ring expansion beyond ring-1 is exact and rare.
__global__ __launch_bounds__(64) void k_knn(const float* __restrict__ gv) {
    __shared__ float4 spos[CAP];
    __shared__ int    sidx[CAP];
    __shared__ int4   srun[27];   // x=staged off, y=len, z=unused, w=pack(dx+1,dy+1,zi)
    __shared__ int    snsub;

    int b = blockIdx.x;
    int cx = b >> 6, cy = (b >> 3) & 7, cz = b & 7;
    int t = threadIdx.x;
    // warp shares a z-slab: lanes vary fastest in x,y
    int sx = t & 3, sy = (t >> 2) & 3, sz = t >> 4;
    int gx = cx * 4 + sx, gy = cy * 4 + sy, gz = cz * 4 + sz;
    int m = (gx * 32 + gy) * 32 + gz;

    float qx = gv[m * 3 + 0] * 32.f;
    float qy = gv[m * 3 + 1] * 32.f;
    float qz = gv[m * 3 + 2] * 32.f;
    float Q = fmaf(qx, qx, fmaf(qy, qy, qz * qz));

    // stage ring-1 neighborhood as 9 contiguous column runs (nearest-first);
    // thread 0 also records the per-z sub-run table.
    const int odx[9] = {0,  1, -1,  0,  0,  1,  1, -1, -1};
    const int ody[9] = {0,  0,  0,  1, -1,  1, -1,  1, -1};
    int nc = 0, ns = 0;
    int zlo = max(cz - 1, 0), zhi = min(cz + 1, 7);
    for (int k = 0; k < 9; k++) {
        int x = cx + odx[k], y = cy + ody[k];
        if ((unsigned)x > 7u || (unsigned)y > 7u) continue;
        int base = (x * 8 + y) * 8;
        int s = __ldg(&d_cellstart[base + zlo]);
        int e = __ldg(&d_cellstart[base + zhi + 1]);
        int len = e - s;
        if (nc + len > CAP) len = CAP - nc;
        for (int i = t; i < len; i += 64) {
            spos[nc + i] = d_spts[s + i];
            sidx[nc + i] = d_sidx[s + i];
        }
        if (t == 0) {
            for (int zi = zlo; zi <= zhi; zi++) {
                int a0 = __ldg(&d_cellstart[base + zi]) - s;
                int a1 = __ldg(&d_cellstart[base + zi + 1]) - s;
                a0 = min(a0, len); a1 = min(a1, len);
                if (a1 > a0) {
                    int w = ((odx[k] + 1) << 5) | ((ody[k] + 1) << 3) | zi;
                    srun[ns] = make_int4(nc + a0, a1 - a0, 0, w);
                    ns++;
                }
            }
        }
        nc += len;
    }
    if (t == 0) snsub = ns;
    __syncthreads();
    int nsub = snsub;

    float bv[16]; int bi[16];
#pragma unroll
    for (int j = 0; j < 16; j++) { bv[j] = 3.4e38f; bi[j] = 0; }

    float xlo = (float)cx * CS, xhi = xlo + CS;
    float ylo = (float)cy * CS, yhi = ylo + CS;

    for (int r = 0; r < nsub; r++) {
        int4 u = srun[r];
        int zi = u.w & 7;
        int dy = ((u.w >> 3) & 3) - 1;
        int dx = (u.w >> 5) - 1;
        float lbx = (dx > 0) ? (xhi - qx) : (dx < 0 ? (qx - xlo) : 0.f);
        float lby = (dy > 0) ? (yhi - qy) : (dy < 0 ? (qy - ylo) : 0.f);
        float lbz = (zi > cz) ? ((float)zi * CS - qz)
                  : (zi < cz ? (qz - (float)(zi + 1) * CS) : 0.f);
        float lb2 = fmaf(lbx, lbx, fmaf(lby, lby, lbz * lbz));
        if (lb2 >= bv[15]) continue;           // whole chunk can't qualify

        int e = u.x + u.y;
        for (int i = u.x; i < e; i++) {
            float4 p = spos[i];
            float dotv = fmaf(qx, p.x, fmaf(qy, p.y, qz * p.z));
            float sc = (Q + p.w) - 2.f * dotv;
            if (sc < bv[15]) ins16(sc, sidx[i], bv, bi);
        }
    }

    // exact ring expansion: covered box after ring rr = cells [c-rr, c+rr]
    for (int rr = 1; rr < 8; rr++) {
        float mlx = (cx - rr > 0) ? qx - (float)(cx - rr) * CS : 1e30f;
        float mhx = (cx + rr < 7) ? (float)(cx + rr + 1) * CS - qx : 1e30f;
        float mly = (cy - rr > 0) ? qy - (float)(cy - rr) * CS : 1e30f;
        float mhy = (cy + rr < 7) ? (float)(cy + rr + 1) * CS - qy : 1e30f;
        float mlz = (cz - rr > 0) ? qz - (float)(cz - rr) * CS : 1e30f;
        float mhz = (cz + rr < 7) ? (float)(cz + rr + 1) * CS - qz : 1e30f;
        float mg = fminf(fminf(fminf(mlx, mhx), fminf(mly, mhy)), fminf(mlz, mhz));
        if (mg > 1e29f) break;                         // whole domain covered
        if (bv[15] <= mg * mg * 0.9999f) break;        // exact (with fp slack)

        int r2 = rr + 1;                               // scan Chebyshev shell r2
        for (int dx = -r2; dx <= r2; dx++) {
            int x = cx + dx;
            if ((unsigned)x > 7u) continue;
            for (int dy = -r2; dy <= r2; dy++) {
                int y = cy + dy;
                if ((unsigned)y > 7u) continue;
                int base = (x * 8 + y) * 8;
                if (max(abs(dx), abs(dy)) == r2) {
                    int zl = max(cz - r2, 0), zh = min(cz + r2, 7);
                    scan_run(__ldg(&d_cellstart[base + zl]),
                             __ldg(&d_cellstart[base + zh + 1]),
                             qx, qy, qz, Q, bv, bi);
                } else {
                    int z = cz - r2;
                    if (z >= 0)
                        scan_run(__ldg(&d_cellstart[base + z]),
                                 __ldg(&d_cellstart[base + z + 1]),
                                 qx, qy, qz, Q, bv, bi);
                    z = cz + r2;
                    if (z <= 7)
                        scan_run(__ldg(&d_cellstart[base + z]),
                                 __ldg(&d_cellstart[base + z + 1]),
                                 qx, qy, qz, Q, bv, bi);
                }
            }
        }
    }

    int4* o = reinterpret_cast<int4*>(d_knn + m * 16);
    o[0] = make_int4(bi[0],  bi[1],  bi[2],  bi[3]);
    o[1] = make_int4(bi[4],  bi[5],  bi[6],  bi[7]);
    o[2] = make_int4(bi[8],  bi[9],  bi[10], bi[11]);
    o[3] = make_int4(bi[12], bi[13], bi[14], bi[15]);
}

// -------------------------------------------------- edge MLP + mean over K
__device__ __forceinline__ float gelu_t(float x) {
    float a = -1.5957691216057308f * x * fmaf(0.044715f, x * x, 1.f);
    float e = __expf(a);
    return __fdividef(x, 1.f + e);
}

__global__ __launch_bounds__(128) void k_edge(const float* __restrict__ verts,
                                              const float* __restrict__ gv,
                                              const float* __restrict__ ew1,
                                              const float* __restrict__ eg1,
                                              const float* __restrict__ ebt1) {
    __shared__ float sW[3 * 64];
    __shared__ float sg[64], sb[64];
    int t = threadIdx.x;
    for (int i = t; i < 192; i += 128) sW[i] = ew1[32 * 64 + i];
    if (t < 64) { sg[t] = eg1[t]; sb[t] = ebt1[t]; }
    __syncthreads();

    int gid = blockIdx.x * 128 + t;
    int m = gid >> 4;
    int idx = d_knn[gid];

    float gx = gv[m * 3 + 0], gy = gv[m * 3 + 1], gz = gv[m * 3 + 2];
    float rx = verts[idx * 3 + 0] - gx;
    float ry = verts[idx * 3 + 1] - gy;
    float rz = verts[idx * 3 + 2] - gz;

    float v[64];
    const float4* pfr = reinterpret_cast<const float4*>(d_pf + (size_t)idx * 64);
#pragma unroll
    for (int j = 0; j < 16; j++) {
        float4 p = pfr[j];
        int c = j * 4;
        v[c + 0] = fmaf(rx, sW[c + 0], fmaf(ry, sW[64 + c + 0], fmaf(rz, sW[128 + c + 0], p.x)));
        v[c + 1] = fmaf(rx, sW[c + 1], fmaf(ry, sW[64 + c + 1], fmaf(rz, sW[128 + c + 1], p.y)));
        v[c + 2] = fmaf(rx, sW[c + 2], fmaf(ry, sW[64 + c + 2], fmaf(rz, sW[128 + c + 2], p.z)));
        v[c + 3] = fmaf(rx, sW[c + 3], fmaf(ry, sW[64 + c + 3], fmaf(rz, sW[128 + c + 3], p.w)));
    }
    float s1 = 0.f;
#pragma unroll
    for (int j = 0; j < 64; j++) s1 += v[j];
    float mu = s1 * (1.f / 64.f);
    float s2 = 0.f;
#pragma unroll
    for (int j = 0; j < 64; j++) { float d = v[j] - mu; s2 = fmaf(d, d, s2); }
    float inv = rsqrtf(s2 * (1.f / 64.f) + 1e-5f);
#pragma unroll
    for (int j = 0; j < 64; j++) {
        float x = fmaf((v[j] - mu) * inv, sg[j], sb[j]);
        v[j] = gelu_t(x);
    }

    // mean over K: exchange-halves butterfly. After 4 steps, lane16 = t&15
    // holds channels [4*lane16, 4*lane16+4) summed over all 16 neighbors.
    int lane16 = t & 15;
#pragma unroll
    for (int halfc = 32; halfc >= 4; halfc >>= 1) {
        int bit = halfc >> 2;             // 8,4,2,1
        bool hi = (lane16 & bit) != 0;
#pragma unroll
        for (int j = 0; j < halfc; j++) {
            float send = hi ? v[j] : v[j + halfc];
            float r = __shfl_xor_sync(0xffffffffu, send, bit);
            v[j] = (hi ? v[j + halfc] : v[j]) + r;
        }
    }
    float4* go = reinterpret_cast<float4*>(d_gmean + (size_t)m * 64);
    go[lane16] = make_float4(v[0] * 0.0625f, v[1] * 0.0625f,
                             v[2] * 0.0625f, v[3] * 0.0625f);
}

// ------------------------------------------------------------- out MLP
__global__ __launch_bounds__(256) void k_out(const float* __restrict__ gfeat,
                                             const float* __restrict__ ow1,
                                             const float* __restrict__ og1,
                                             const float* __restrict__ obt1,
                                             const float* __restrict__ ow2,
                                             const float* __restrict__ ob2,
                                             float* __restrict__ out) {
    extern __shared__ float smem[];
    float* sWf  = smem;
    float* sW1b = sWf + 4096;
    float* sW2  = sW1b + 6144;
    float* sbf  = sW2 + 4096;
    float* sg1  = sbf + 64;
    float* sbt  = sg1 + 64;
    float* sb2  = sbt + 64;
    float* sbuf = sb2 + 64;

    int t = threadIdx.x;
    for (int i = t; i < 4096; i += 256) { sWf[i] = d_Wf[i]; sW2[i] = ow2[i]; }
    for (int i = t; i < 6144; i += 256) sW1b[i] = ow1[64 * 64 + i];
    if (t < 64) { sbf[t] = d_bf[t]; sg1[t] = og1[t]; sbt[t] = obt1[t]; sb2[t] = ob2[t]; }
    __syncthreads();

    int w = t >> 5, lane = t & 31;
    int mbase = blockIdx.x * 32 + w * 4;
    float* buf = sbuf + (w * 4) * 160;

#pragma unroll
    for (int q = 0; q < 4; q++) {
        int m = mbase + q;
        for (int i = lane; i < 64; i += 32) buf[q * 160 + i] = d_gmean[(size_t)m * 64 + i];
        for (int i = lane; i < 96; i += 32) buf[q * 160 + 64 + i] = gfeat[(size_t)m * 96 + i];
    }
    __syncwarp();

    int c0 = 2 * lane;
    float2 acc[4];
#pragma unroll
    for (int q = 0; q < 4; q++) acc[q] = make_float2(sbf[c0], sbf[c0 + 1]);

#pragma unroll 4
    for (int j = 0; j < 64; j++) {
        float2 wv = *reinterpret_cast<float2*>(&sWf[j * 64 + c0]);
#pragma unroll
        for (int q = 0; q < 4; q++) {
            float x = buf[q * 160 + j];
            acc[q].x = fmaf(x, wv.x, acc[q].x);
            acc[q].y = fmaf(x, wv.y, acc[q].y);
        }
    }
#pragma unroll 4
    for (int j = 0; j < 96; j++) {
        float2 wv = *reinterpret_cast<float2*>(&sW1b[j * 64 + c0]);
#pragma unroll
        for (int q = 0; q < 4; q++) {
            float x = buf[q * 160 + 64 + j];
            acc[q].x = fmaf(x, wv.x, acc[q].x);
            acc[q].y = fmaf(x, wv.y, acc[q].y);
        }
    }
    __syncwarp();

    float ga = sg1[c0], gb = sg1[c0 + 1], ba = sbt[c0], bb = sbt[c0 + 1];
#pragma unroll
    for (int q = 0; q < 4; q++) {
        float s1 = acc[q].x + acc[q].y;
        float s2 = fmaf(acc[q].x, acc[q].x, acc[q].y * acc[q].y);
#pragma unroll
        for (int off = 16; off > 0; off >>= 1) {
            s1 += __shfl_xor_sync(0xffffffffu, s1, off);
            s2 += __shfl_xor_sync(0xffffffffu, s2, off);
        }
        float mu  = s1 * (1.f / 64.f);
        float var = s2 * (1.f / 64.f) - mu * mu;
        float inv = rsqrtf(var + 1e-5f);
        float x0 = fmaf((acc[q].x - mu) * inv, ga, ba);
        float x1 = fmaf((acc[q].y - mu) * inv, gb, bb);
        buf[q * 160 + c0]     = gelu_t(x0);
        buf[q * 160 + c0 + 1] = gelu_t(x1);
    }
    __syncwarp();

    float2 o[4];
#pragma unroll
    for (int q = 0; q < 4; q++) o[q] = make_float2(sb2[c0], sb2[c0 + 1]);
#pragma unroll 4
    for (int j = 0; j < 64; j++) {
        float2 wv = *reinterpret_cast<float2*>(&sW2[j * 64 + c0]);
#pragma unroll
        for (int q = 0; q < 4; q++) {
            float x = buf[q * 160 + j];
            o[q].x = fmaf(x, wv.x, o[q].x);
            o[q].y = fmaf(x, wv.y, o[q].y);
        }
    }
#pragma unroll
    for (int q = 0; q < 4; q++) {
        int m = mbase + q;
        *reinterpret_cast<float2*>(&out[(size_t)m * 64 + c0]) = o[q];
    }
}

// ------------------------------------------------------------------ launch
extern "C" void kernel_launch(void* const* d_in, const int* in_sizes, int n_in,
                              void* d_out, int out_size) {
    const float* vertices = (const float*)d_in[0];
    const float* features = (const float*)d_in[1];
    const float* grid_v   = (const float*)d_in[2];
    const float* grid_f   = (const float*)d_in[3];
    const float* ew1  = (const float*)d_in[4];
    const float* eb1  = (const float*)d_in[5];
    const float* eg1  = (const float*)d_in[6];
    const float* ebt1 = (const float*)d_in[7];
    const float* ew2  = (const float*)d_in[8];
    const float* eb2  = (const float*)d_in[9];
    const float* ow1  = (const float*)d_in[10];
    const float* ob1  = (const float*)d_in[11];
    const float* og1  = (const float*)d_in[12];
    const float* obt1 = (const float*)d_in[13];
    const float* ow2  = (const float*)d_in[14];
    const float* ob2  = (const float*)d_in[15];
    float* out = (float*)d_out;

    const int OUT_SMEM = (4096 + 6144 + 4096 + 4 * 64 + 32 * 160) * (int)sizeof(float);
    cudaFuncSetAttribute(k_out, cudaFuncAttributeMaxDynamicSharedMemorySize, OUT_SMEM);

    k_bin<<<1, 1024>>>(vertices);                                   // 0
    k_pf<<<(N_PTS * COUT + 255) / 256, 256>>>(features, ew1, eb1);  // 1
    k_knn<<<NCELLS, 64>>>(grid_v);                                  // 2
    k_edge<<<(M_GRID * KNN) / 128, 128>>>(vertices, grid_v, ew1, eg1, ebt1); // 3 (profiled)
    k_fuse<<<16, 256>>>(ew2, eb2, ow1, ob1);                        // 4
    k_out<<<M_GRID / 32, 256, OUT_SMEM>>>(grid_f, ow1, og1, obt1, ow2, ob2, out); // 5
}